// round 13
// baseline (speedup 1.0000x reference)
#include <cuda_runtime.h>
#include <cuda_fp16.h>
#include <math.h>
#include <stdint.h>

#define NN 50000
#define EE 800000
#define ET (EE + NN)
#define GG 32
#define SCAN_B 512
#define NSCAN ((NN + SCAN_B - 1) / SCAN_B)   // 98
#define WOFF 32768                           // max K*N per weight matrix

// ---------------- scratch (device globals; no allocation allowed) ----------
__device__ float  g_xl[NN * 256];
__device__ float  g_xr[NN * 256];
__device__ float  g_b1[NN * 256];
__device__ float  g_b2[NN * 256];
__device__ __half g_wth[2 * WOFF];   // transposed weights, fp16 hi (Wl @0, Wr @WOFF)
__device__ __half g_wtl[2 * WOFF];   // transposed weights, fp16 lo
__device__ int    g_deg[NN];
__device__ int    g_rowptr[NN + 1];
__device__ int    g_cursor[NN];
__device__ int    g_csrc[ET];
__device__ int    g_bsum[128];
__device__ int    g_boff[128];
__device__ float  g_sum[GG * 256];
__device__ float  g_sq[GG * 256];
__device__ float  g_cs[GG * 256];
__device__ float  g_ct[GG * 256];
__device__ float  g_cnt[GG];
__device__ float  g_feat[GG * 16];

// ---------------- helpers ----------------------------------------------------
__device__ __forceinline__ void split_h(float v, __half& h, __half& l) {
    h = __float2half_rn(v);
    l = __float2half_rn(v - __half2float(h));
}
__device__ __forceinline__ float lrelu(float m) {
    return m > 0.f ? m : 0.2f * m;
}
__device__ __forceinline__ void mma16816(float* c, const uint32_t* a, const uint32_t* b) {
    asm volatile(
        "mma.sync.aligned.m16n8k16.row.col.f32.f16.f16.f32 "
        "{%0,%1,%2,%3}, {%4,%5,%6,%7}, {%8,%9}, {%0,%1,%2,%3};"
        : "+f"(c[0]), "+f"(c[1]), "+f"(c[2]), "+f"(c[3])
        : "r"(a[0]), "r"(a[1]), "r"(a[2]), "r"(a[3]), "r"(b[0]), "r"(b[1]));
}

// transpose + hi/lo split both weight matrices of a layer
__global__ void k_cvtB2(const float* __restrict__ W0, const float* __restrict__ W1,
                        int K, int Nn) {
    int total = K * Nn;
    int i = blockIdx.x * blockDim.x + threadIdx.x;
    if (i < 2 * total) {
        int m = i >= total;
        int j = i - m * total;
        int k = j / Nn, n = j - k * Nn;
        float v = (m ? W1 : W0)[j];
        __half h, l;
        split_h(v, h, l);
        int dst = m * WOFF + n * K + k;
        g_wth[dst] = h;
        g_wtl[dst] = l;
    }
}

// ---------------- CSR build --------------------------------------------------
__global__ void k_init_deg() {
    int i = blockIdx.x * blockDim.x + threadIdx.x;
    if (i < NN) g_deg[i] = 1;  // self loop
}

__global__ void k_count(const int* __restrict__ ei) {
    int e = blockIdx.x * blockDim.x + threadIdx.x;
    if (e < EE) atomicAdd(&g_deg[ei[EE + e]], 1);
}

__global__ void k_scan_blk() {
    __shared__ int wsum[16];
    const int b = blockIdx.x, t = threadIdx.x, lane = t & 31, w = t >> 5;
    const int i = b * SCAN_B + t;
    int v = (i < NN) ? g_deg[i] : 0;
    int s = v;
#pragma unroll
    for (int o = 1; o < 32; o <<= 1) {
        int u = __shfl_up_sync(0xffffffffu, s, o);
        if (lane >= o) s += u;
    }
    if (lane == 31) wsum[w] = s;
    __syncthreads();
    if (w == 0) {
        int ws = (lane < 16) ? wsum[lane] : 0;
        int t2 = ws;
#pragma unroll
        for (int o = 1; o < 32; o <<= 1) {
            int u = __shfl_up_sync(0xffffffffu, t2, o);
            if (lane >= o) t2 += u;
        }
        if (lane < 16) wsum[lane] = t2 - ws;
    }
    __syncthreads();
    if (i < NN) g_rowptr[i] = wsum[w] + s - v;
    if (t == SCAN_B - 1) g_bsum[b] = wsum[15] + s;
}

__global__ void k_scan_top() {
    __shared__ int wsum[4];
    const int t = threadIdx.x, lane = t & 31, w = t >> 5;
    int v = (t < NSCAN) ? g_bsum[t] : 0;
    int s = v;
#pragma unroll
    for (int o = 1; o < 32; o <<= 1) {
        int u = __shfl_up_sync(0xffffffffu, s, o);
        if (lane >= o) s += u;
    }
    if (lane == 31) wsum[w] = s;
    __syncthreads();
    if (w == 0) {
        int ws = (lane < 4) ? wsum[lane] : 0;
        int t2 = ws;
#pragma unroll
        for (int o = 1; o < 32; o <<= 1) {
            int u = __shfl_up_sync(0xffffffffu, t2, o);
            if (lane >= o) t2 += u;
        }
        if (lane < 4) wsum[lane] = t2 - ws;
    }
    __syncthreads();
    if (t < NSCAN) g_boff[t] = wsum[w] + s - v;
    if (t == 127) g_rowptr[NN] = wsum[3] + s;
}

__global__ void k_scan_add() {
    int i = blockIdx.x * blockDim.x + threadIdx.x;
    if (i < NN) {
        int r = g_rowptr[i] + g_boff[i / SCAN_B];
        g_rowptr[i] = r;
        g_cursor[i] = r;
    }
}

__global__ void k_scatter(const int* __restrict__ ei) {
    int e = blockIdx.x * blockDim.x + threadIdx.x;
    if (e < ET) {
        int s, d;
        if (e < EE) { s = ei[e]; d = ei[EE + e]; }
        else        { s = d = e - EE; }
        int p = atomicAdd(&g_cursor[d], 1);
        g_csrc[p] = s;
    }
}

__global__ void k_count_batch(const int* __restrict__ batch) {
    int i = blockIdx.x * blockDim.x + threadIdx.x;
    if (i < NN) atomicAdd(&g_cnt[batch[i]], 1.0f);
}

// ---------------- HMMA fp16-3x GEMM (R10 measured-best form) ------------------
#define APAD 20

__global__ void __launch_bounds__(256)
k_gemm_mma(const float* __restrict__ A,
           const float* __restrict__ bias0, const float* __restrict__ bias1,
           float* __restrict__ C0, float* __restrict__ C1,
           int M, int K, int Nn) {
    const float* bias = blockIdx.z ? bias1 : bias0;
    float*       C    = blockIdx.z ? C1 : C0;
    const __half* WTh = g_wth + (blockIdx.z ? WOFF : 0);
    const __half* WTl = g_wtl + (blockIdx.z ? WOFF : 0);

    __shared__ alignas(16) __half Ah[128 * APAD], Al[128 * APAD];
    __shared__ alignas(16) __half Bh[64 * APAD],  Bl[64 * APAD];

    const int tid = threadIdx.x, lane = tid & 31, wid = tid >> 5;
    const int row0 = blockIdx.y * 128, col0 = blockIdx.x * 64;
    const int wm = wid >> 1, wn = wid & 1;
    const int fr = lane >> 2, fc = (lane & 3) * 2;

    const int ar = tid >> 1, akq = (tid & 1) * 8;

    float acc[2][4][4];
#pragma unroll
    for (int i = 0; i < 2; i++)
#pragma unroll
        for (int j = 0; j < 4; j++)
#pragma unroll
            for (int q = 0; q < 4; q++) acc[i][j][q] = 0.f;

    const int nkc = K >> 4;
    for (int kc = 0; kc < nkc; kc++) {
        float4 v0, v1;
        const float* Ap = A + (size_t)(row0 + ar) * K + kc * 16 + akq;
        if (row0 + ar < M) { v0 = *(const float4*)Ap; v1 = *(const float4*)(Ap + 4); }
        else { v0 = make_float4(0.f, 0.f, 0.f, 0.f); v1 = v0; }
        uint2 bv0, bv1;
        int i0 = tid, i1 = tid + 256;
        {
            int n = i0 >> 3, sub = i0 & 7;
            const __half* src = (sub & 4 ? WTl : WTh) +
                                (size_t)(col0 + n) * K + kc * 16 + (sub & 3) * 4;
            bv0 = *(const uint2*)src;
        }
        {
            int n = i1 >> 3, sub = i1 & 7;
            const __half* src = (sub & 4 ? WTl : WTh) +
                                (size_t)(col0 + n) * K + kc * 16 + (sub & 3) * 4;
            bv1 = *(const uint2*)src;
        }

        __syncthreads();

        {
            float av[8] = {v0.x, v0.y, v0.z, v0.w, v1.x, v1.y, v1.z, v1.w};
            int base = ar * APAD + akq;
#pragma unroll
            for (int j = 0; j < 8; j += 2) {
                __half h0, h1, l0, l1;
                split_h(av[j], h0, l0);
                split_h(av[j + 1], h1, l1);
                *(__half2*)&Ah[base + j] = __halves2half2(h0, h1);
                *(__half2*)&Al[base + j] = __halves2half2(l0, l1);
            }
        }
        {
            int n = i0 >> 3, sub = i0 & 7;
            __half* dst = (sub & 4 ? Bl : Bh) + n * APAD + (sub & 3) * 4;
            *(uint2*)dst = bv0;
        }
        {
            int n = i1 >> 3, sub = i1 & 7;
            __half* dst = (sub & 4 ? Bl : Bh) + n * APAD + (sub & 3) * 4;
            *(uint2*)dst = bv1;
        }
        __syncthreads();

        uint32_t ah[2][4], al[2][4], bh[4][2], bl[4][2];
#pragma unroll
        for (int ma = 0; ma < 2; ma++) {
            int r = wm * 32 + ma * 16 + fr;
            ah[ma][0] = *(const uint32_t*)&Ah[r * APAD + fc];
            ah[ma][1] = *(const uint32_t*)&Ah[(r + 8) * APAD + fc];
            ah[ma][2] = *(const uint32_t*)&Ah[r * APAD + fc + 8];
            ah[ma][3] = *(const uint32_t*)&Ah[(r + 8) * APAD + fc + 8];
            al[ma][0] = *(const uint32_t*)&Al[r * APAD + fc];
            al[ma][1] = *(const uint32_t*)&Al[(r + 8) * APAD + fc];
            al[ma][2] = *(const uint32_t*)&Al[r * APAD + fc + 8];
            al[ma][3] = *(const uint32_t*)&Al[(r + 8) * APAD + fc + 8];
        }
#pragma unroll
        for (int na = 0; na < 4; na++) {
            int cn = wn * 32 + na * 8 + fr;
            bh[na][0] = *(const uint32_t*)&Bh[cn * APAD + fc];
            bh[na][1] = *(const uint32_t*)&Bh[cn * APAD + fc + 8];
            bl[na][0] = *(const uint32_t*)&Bl[cn * APAD + fc];
            bl[na][1] = *(const uint32_t*)&Bl[cn * APAD + fc + 8];
        }
#pragma unroll
        for (int ma = 0; ma < 2; ma++)
#pragma unroll
            for (int na = 0; na < 4; na++) {
                mma16816(acc[ma][na], ah[ma], bh[na]);
                mma16816(acc[ma][na], ah[ma], bl[na]);
                mma16816(acc[ma][na], al[ma], bh[na]);
            }
    }

#pragma unroll
    for (int ma = 0; ma < 2; ma++)
#pragma unroll
        for (int na = 0; na < 4; na++) {
            int r = row0 + wm * 32 + ma * 16 + fr;
            int c = col0 + wn * 32 + na * 8 + fc;
            float2 bb = *(const float2*)&bias[c];
            if (r < M)
                *(float2*)&C[(size_t)r * Nn + c] =
                    make_float2(acc[ma][na][0] + bb.x, acc[ma][na][1] + bb.y);
            if (r + 8 < M)
                *(float2*)&C[(size_t)(r + 8) * Nn + c] =
                    make_float2(acc[ma][na][2] + bb.x, acc[ma][na][3] + bb.y);
        }
}

// ---------------- GATv2 attention: head-aligned lanes (R12 measured-best) ----
template <int D, bool CONCAT>
__global__ void k_attn(const float* __restrict__ xl, const float* __restrict__ xr,
                       const float* __restrict__ att, const float* __restrict__ bias,
                       float* __restrict__ out) {
    constexpr int HD = 4 * D;
    constexpr int NW = HD / 32;
    const int node = blockIdx.x;
    const int tid = threadIdx.x, lane = tid & 31, w = tid >> 5;
    __shared__ float sden[NW][4];
    __shared__ float sacc[NW][HD];
    __shared__ float sinv[4];

    const int beg = g_rowptr[node], end = g_rowptr[node + 1];
    const float* xrp = xr + (size_t)node * HD;

    if (D == 64) {
        float4 rx0 = *(const float4*)&xrp[4 * lane];
        float4 rx1 = *(const float4*)&xrp[128 + 4 * lane];
        float4 ra0 = *(const float4*)&att[4 * lane];
        float4 ra1 = *(const float4*)&att[128 + 4 * lane];
        float acc0[4] = {0.f, 0.f, 0.f, 0.f}, acc1[4] = {0.f, 0.f, 0.f, 0.f};
        float dena = 0.f, denb = 0.f;
        for (int e = beg + w; e < end; e += NW) {
            const float* xs = xl + (size_t)g_csrc[e] * 256;
            float4 x0 = *(const float4*)&xs[4 * lane];
            float4 x1 = *(const float4*)&xs[128 + 4 * lane];
            float pa = lrelu(x0.x + rx0.x) * ra0.x;
            pa = fmaf(lrelu(x0.y + rx0.y), ra0.y, pa);
            pa = fmaf(lrelu(x0.z + rx0.z), ra0.z, pa);
            pa = fmaf(lrelu(x0.w + rx0.w), ra0.w, pa);
            float pb = lrelu(x1.x + rx1.x) * ra1.x;
            pb = fmaf(lrelu(x1.y + rx1.y), ra1.y, pb);
            pb = fmaf(lrelu(x1.z + rx1.z), ra1.z, pb);
            pb = fmaf(lrelu(x1.w + rx1.w), ra1.w, pb);
#pragma unroll
            for (int o = 8; o; o >>= 1) {
                pa += __shfl_xor_sync(0xffffffffu, pa, o);
                pb += __shfl_xor_sync(0xffffffffu, pb, o);
            }
            float wa = __expf(pa), wb = __expf(pb);
            dena += wa; denb += wb;
            acc0[0] = fmaf(wa, x0.x, acc0[0]); acc0[1] = fmaf(wa, x0.y, acc0[1]);
            acc0[2] = fmaf(wa, x0.z, acc0[2]); acc0[3] = fmaf(wa, x0.w, acc0[3]);
            acc1[0] = fmaf(wb, x1.x, acc1[0]); acc1[1] = fmaf(wb, x1.y, acc1[1]);
            acc1[2] = fmaf(wb, x1.z, acc1[2]); acc1[3] = fmaf(wb, x1.w, acc1[3]);
        }
        *(float4*)&sacc[w][4 * lane] = make_float4(acc0[0], acc0[1], acc0[2], acc0[3]);
        *(float4*)&sacc[w][128 + 4 * lane] = make_float4(acc1[0], acc1[1], acc1[2], acc1[3]);
        if (lane == 0)  { sden[w][0] = dena; sden[w][2] = denb; }
        if (lane == 16) { sden[w][1] = dena; sden[w][3] = denb; }
    } else if (D == 32) {
        float4 rx = *(const float4*)&xrp[4 * lane];
        float4 ra = *(const float4*)&att[4 * lane];
        float acc[4] = {0.f, 0.f, 0.f, 0.f};
        float den = 0.f;
        for (int e = beg + w; e < end; e += NW) {
            const float* xs = xl + (size_t)g_csrc[e] * 128;
            float4 x0 = *(const float4*)&xs[4 * lane];
            float p = lrelu(x0.x + rx.x) * ra.x;
            p = fmaf(lrelu(x0.y + rx.y), ra.y, p);
            p = fmaf(lrelu(x0.z + rx.z), ra.z, p);
            p = fmaf(lrelu(x0.w + rx.w), ra.w, p);
#pragma unroll
            for (int o = 4; o; o >>= 1) p += __shfl_xor_sync(0xffffffffu, p, o);
            float wg = __expf(p);
            den += wg;
            acc[0] = fmaf(wg, x0.x, acc[0]); acc[1] = fmaf(wg, x0.y, acc[1]);
            acc[2] = fmaf(wg, x0.z, acc[2]); acc[3] = fmaf(wg, x0.w, acc[3]);
        }
        *(float4*)&sacc[w][4 * lane] = make_float4(acc[0], acc[1], acc[2], acc[3]);
        if ((lane & 7) == 0) sden[w][lane >> 3] = den;
    } else {
        float2 rx = *(const float2*)&xrp[2 * lane];
        float2 ra = *(const float2*)&att[2 * lane];
        float acc[2] = {0.f, 0.f};
        float den = 0.f;
        for (int e = beg + w; e < end; e += NW) {
            const float* xs = xl + (size_t)g_csrc[e] * 64;
            float2 x0 = *(const float2*)&xs[2 * lane];
            float p = lrelu(x0.x + rx.x) * ra.x;
            p = fmaf(lrelu(x0.y + rx.y), ra.y, p);
#pragma unroll
            for (int o = 4; o; o >>= 1) p += __shfl_xor_sync(0xffffffffu, p, o);
            float wg = __expf(p);
            den += wg;
            acc[0] = fmaf(wg, x0.x, acc[0]); acc[1] = fmaf(wg, x0.y, acc[1]);
        }
        *(float2*)&sacc[w][2 * lane] = make_float2(acc[0], acc[1]);
        if ((lane & 7) == 0) sden[w][lane >> 3] = den;
    }
    __syncthreads();

    if (tid < 4) {
        float dt = 0.f;
#pragma unroll
        for (int i = 0; i < NW; i++) dt += sden[i][tid];
        sinv[tid] = 1.f / (dt + 1e-16f);
    }
    __syncthreads();

    {
        const int c = tid, h = c / D;
        float a = 0.f;
#pragma unroll
        for (int i = 0; i < NW; i++) a += sacc[i][c];
        float r = a * sinv[h];
        if (CONCAT) {
            out[(size_t)node * HD + c] = r + bias[c];
        } else {
            __syncthreads();
            sacc[0][c] = r;
        }
    }
    if (!CONCAT) {
        __syncthreads();
        if (tid < D)
            out[(size_t)node * D + tid] =
                0.25f * (sacc[0][tid] + sacc[0][D + tid] + sacc[0][2 * D + tid] + sacc[0][3 * D + tid]) + bias[tid];
    }
}

// ---------------- GraphNorm ---------------------------------------------------
// float4-vectorized sum/sumsq reduce: thread owns one 16B column slice,
// flush-on-group-change (batch is sorted). 4x fewer load instructions than
// the scalar version (which was LSU-issue-bound at ~1.82cyc/LDG).
#define GN_CHUNK 64
__global__ void k_gn_reduce(const float* __restrict__ x, const int* __restrict__ batch,
                            int F) {
    __shared__ int sb[GN_CHUNK];
    const int tid = threadIdx.x;
    const int Fq = F >> 2;            // float4 slots per node (64 / 32 / 4)
    const int R = 256 / Fq;           // node slices per block (4 / 8 / 64)
    const int f4 = (tid % Fq) * 4;    // channel offset of this thread's float4
    const int r = tid / Fq;
    const int n0 = blockIdx.x * GN_CHUNK;
    if (tid < GN_CHUNK) sb[tid] = (n0 + tid < NN) ? batch[n0 + tid] : -1;
    __syncthreads();
    float4 s = make_float4(0.f, 0.f, 0.f, 0.f);
    float4 q = make_float4(0.f, 0.f, 0.f, 0.f);
    int cg = -1;
    for (int i = r; i < GN_CHUNK && n0 + i < NN; i += R) {
        int g = sb[i];
        if (g != cg) {
            if (cg >= 0) {
                atomicAdd(&g_sum[cg * F + f4 + 0], s.x);
                atomicAdd(&g_sum[cg * F + f4 + 1], s.y);
                atomicAdd(&g_sum[cg * F + f4 + 2], s.z);
                atomicAdd(&g_sum[cg * F + f4 + 3], s.w);
                atomicAdd(&g_sq[cg * F + f4 + 0], q.x);
                atomicAdd(&g_sq[cg * F + f4 + 1], q.y);
                atomicAdd(&g_sq[cg * F + f4 + 2], q.z);
                atomicAdd(&g_sq[cg * F + f4 + 3], q.w);
            }
            s = make_float4(0.f, 0.f, 0.f, 0.f);
            q = make_float4(0.f, 0.f, 0.f, 0.f);
            cg = g;
        }
        float4 v = *(const float4*)&x[(size_t)(n0 + i) * F + f4];
        s.x += v.x; s.y += v.y; s.z += v.z; s.w += v.w;
        q.x = fmaf(v.x, v.x, q.x); q.y = fmaf(v.y, v.y, q.y);
        q.z = fmaf(v.z, v.z, q.z); q.w = fmaf(v.w, v.w, q.w);
    }
    if (cg >= 0) {
        atomicAdd(&g_sum[cg * F + f4 + 0], s.x);
        atomicAdd(&g_sum[cg * F + f4 + 1], s.y);
        atomicAdd(&g_sum[cg * F + f4 + 2], s.z);
        atomicAdd(&g_sum[cg * F + f4 + 3], s.w);
        atomicAdd(&g_sq[cg * F + f4 + 0], q.x);
        atomicAdd(&g_sq[cg * F + f4 + 1], q.y);
        atomicAdd(&g_sq[cg * F + f4 + 2], q.z);
        atomicAdd(&g_sq[cg * F + f4 + 3], q.w);
    }
}

__global__ void k_gn_coef(const float* __restrict__ w, const float* __restrict__ b,
                          const float* __restrict__ a, int F) {
    int i = blockIdx.x * blockDim.x + threadIdx.x;
    if (i < GG * F) {
        int f = i % F;
        float c = fmaxf(g_cnt[i / F], 1.0f);
        float mean = g_sum[i] / c;
        float av = a[f];
        float var = g_sq[i] / c + mean * mean * (av * av - 2.f * av);
        var = fmaxf(var, 0.f);
        float s = w[f] * rsqrtf(var + 1e-5f);
        g_cs[i] = s;
        g_ct[i] = b[f] - s * av * mean;
        g_sum[i] = 0.f;
        g_sq[i] = 0.f;
    }
}

__global__ void k_gn_apply(float* __restrict__ x, const int* __restrict__ batch, int F) {
    int Fq = F >> 2;
    int idx = blockIdx.x * blockDim.x + threadIdx.x;
    if (idx < NN * Fq) {
        int n = idx / Fq, f4 = (idx - n * Fq) * 4;
        int g = batch[n];
        float4 xv = *(float4*)&x[(size_t)n * F + f4];
        float4 s = *(const float4*)&g_cs[g * F + f4];
        float4 t = *(const float4*)&g_ct[g * F + f4];
        float4 y;
        y.x = fmaxf(fmaf(s.x, xv.x, t.x), 0.f);
        y.y = fmaxf(fmaf(s.y, xv.y, t.y), 0.f);
        y.z = fmaxf(fmaf(s.z, xv.z, t.z), 0.f);
        y.w = fmaxf(fmaf(s.w, xv.w, t.w), 0.f);
        *(float4*)&x[(size_t)n * F + f4] = y;
    }
}

__global__ void k_gn_apply_pool(const float* __restrict__ x, const int* __restrict__ batch) {
    const int F = 16, Fq = 4;
    int idx = blockIdx.x * blockDim.x + threadIdx.x;
    if (idx < NN * Fq) {
        int n = idx / Fq, f4 = (idx - n * Fq) * 4;
        int g = batch[n];
        float4 xv = *(const float4*)&x[(size_t)n * F + f4];
        float4 s = *(const float4*)&g_cs[g * F + f4];
        float4 t = *(const float4*)&g_ct[g * F + f4];
        atomicAdd(&g_feat[g * 16 + f4 + 0], fmaxf(fmaf(s.x, xv.x, t.x), 0.f));
        atomicAdd(&g_feat[g * 16 + f4 + 1], fmaxf(fmaf(s.y, xv.y, t.y), 0.f));
        atomicAdd(&g_feat[g * 16 + f4 + 2], fmaxf(fmaf(s.z, xv.z, t.z), 0.f));
        atomicAdd(&g_feat[g * 16 + f4 + 3], fmaxf(fmaf(s.w, xv.w, t.w), 0.f));
    }
}

// ---------------- classifier head ---------------------------------------------
__global__ void k_head(const float* __restrict__ linW, const float* __restrict__ linB,
                       float* __restrict__ out) {
    __shared__ float sf[GG * 16];
    int tid = threadIdx.x;
    if (tid < GG * 16) {
        int g = tid / 16;
        float v = g_feat[tid] / fmaxf(g_cnt[g], 1.0f);
        sf[tid] = v;
        out[GG * 4 + tid] = v;
        g_feat[tid] = 0.f;
    }
    if (tid < GG) g_cnt[tid] = 0.f;
    __syncthreads();
    if (tid < GG * 4) {
        int g = tid >> 2, c = tid & 3;
        float s = linB[c];
#pragma unroll
        for (int f = 0; f < 16; f++) s = fmaf(sf[g * 16 + f], linW[f * 4 + c], s);
        out[g * 4 + c] = s;
    }
}

// ---------------- host orchestration ------------------------------------------
static void run_gemm2(const float* A, const float* bias0, const float* bias1,
                      float* C0, float* C1, int M, int K, int Nn) {
    dim3 grid(Nn / 64, (M + 127) / 128, 2);
    k_gemm_mma<<<grid, 256>>>(A, bias0, bias1, C0, C1, M, K, Nn);
}

extern "C" void kernel_launch(void* const* d_in, const int* in_sizes, int n_in,
                              void* d_out, int out_size) {
    const float* x     = (const float*)d_in[0];
    const int*   ei    = (const int*)d_in[1];
    const int*   batch = (const int*)d_in[2];
    const float* Wl1 = (const float*)d_in[3],  *bl1 = (const float*)d_in[4];
    const float* Wr1 = (const float*)d_in[5],  *br1 = (const float*)d_in[6];
    const float* att1 = (const float*)d_in[7], *bias1 = (const float*)d_in[8];
    const float* gw1 = (const float*)d_in[9],  *gb1 = (const float*)d_in[10], *ga1 = (const float*)d_in[11];
    const float* Wl2 = (const float*)d_in[12], *bl2 = (const float*)d_in[13];
    const float* Wr2 = (const float*)d_in[14], *br2 = (const float*)d_in[15];
    const float* att2 = (const float*)d_in[16], *bias2 = (const float*)d_in[17];
    const float* gw2 = (const float*)d_in[18], *gb2 = (const float*)d_in[19], *ga2 = (const float*)d_in[20];
    const float* Wl3 = (const float*)d_in[21], *bl3 = (const float*)d_in[22];
    const float* Wr3 = (const float*)d_in[23], *br3 = (const float*)d_in[24];
    const float* att3 = (const float*)d_in[25], *bias3 = (const float*)d_in[26];
    const float* gw3 = (const float*)d_in[27], *gb3 = (const float*)d_in[28], *ga3 = (const float*)d_in[29];
    const float* linW = (const float*)d_in[30], *linB = (const float*)d_in[31];

    float *xl, *xr, *b1, *b2;
    cudaGetSymbolAddress((void**)&xl, g_xl);
    cudaGetSymbolAddress((void**)&xr, g_xr);
    cudaGetSymbolAddress((void**)&b1, g_b1);
    cudaGetSymbolAddress((void**)&b2, g_b2);

    // launches 0-2
    k_cvtB2<<<(2 * 128 * 256 + 255) / 256, 256>>>(Wl1, Wr1, 128, 256);
    k_init_deg<<<(NN + 255) / 256, 256>>>();
    k_count<<<(EE + 255) / 256, 256>>>(ei);

    // launch 3: layer-1 dual GEMM (profiled position)
    run_gemm2(x, bl1, br1, xl, xr, NN, 128, 256);

    // finish CSR
    k_scan_blk<<<NSCAN, SCAN_B>>>();
    k_scan_top<<<1, 128>>>();
    k_scan_add<<<(NN + 255) / 256, 256>>>();
    k_scatter<<<(ET + 255) / 256, 256>>>(ei);
    k_count_batch<<<(NN + 255) / 256, 256>>>(batch);

    // ---- layer 1: 128 -> 4x64 concat (256) ----
    k_attn<64, true><<<NN, 256>>>(xl, xr, att1, bias1, b1);
    k_gn_reduce<<<(NN + GN_CHUNK - 1) / GN_CHUNK, 256>>>(b1, batch, 256);
    k_gn_coef<<<(GG * 256 + 255) / 256, 256>>>(gw1, gb1, ga1, 256);
    k_gn_apply<<<(NN * 64 + 255) / 256, 256>>>(b1, batch, 256);

    // ---- layer 2: 256 -> 4x32 concat (128) ----
    k_cvtB2<<<(2 * 256 * 128 + 255) / 256, 256>>>(Wl2, Wr2, 256, 128);
    run_gemm2(b1, bl2, br2, xl, xr, NN, 256, 128);
    k_attn<32, true><<<NN, 128>>>(xl, xr, att2, bias2, b2);
    k_gn_reduce<<<(NN + GN_CHUNK - 1) / GN_CHUNK, 256>>>(b2, batch, 128);
    k_gn_coef<<<(GG * 128 + 255) / 256, 256>>>(gw2, gb2, ga2, 128);
    k_gn_apply<<<(NN * 32 + 255) / 256, 256>>>(b2, batch, 128);

    // ---- layer 3: 128 -> 4x16 averaged (16) ----
    k_cvtB2<<<(2 * 128 * 64 + 255) / 256, 256>>>(Wl3, Wr3, 128, 64);
    run_gemm2(b2, bl3, br3, xl, xr, NN, 128, 64);
    k_attn<16, false><<<NN, 64>>>(xl, xr, att3, bias3, b1);
    k_gn_reduce<<<(NN + GN_CHUNK - 1) / GN_CHUNK, 256>>>(b1, batch, 16);
    k_gn_coef<<<(GG * 16 + 255) / 256, 256>>>(gw3, gb3, ga3, 16);
    k_gn_apply_pool<<<(NN * 4 + 255) / 256, 256>>>(b1, batch);

    // ---- head ----
    k_head<<<1, 512>>>(linW, linB, (float*)d_out);
}

// round 14
// speedup vs baseline: 1.1025x; 1.1025x over previous
#include <cuda_runtime.h>
#include <cuda_fp16.h>
#include <math.h>
#include <stdint.h>

#define NN 50000
#define EE 800000
#define ET (EE + NN)
#define GG 32
#define SCAN_B 512
#define NSCAN ((NN + SCAN_B - 1) / SCAN_B)   // 98
#define WOFF 32768                           // max K*N per weight matrix

// ---------------- scratch (device globals; no allocation allowed) ----------
__device__ float  g_xl[NN * 256];
__device__ float  g_xr[NN * 256];
__device__ float  g_b1[NN * 256];
__device__ float  g_b2[NN * 256];
__device__ __half g_ah[NN * 256];    // GEMM A operand, fp16 hi
__device__ __half g_al[NN * 256];    // GEMM A operand, fp16 lo
__device__ __half g_wth[2 * WOFF];   // transposed weights, fp16 hi (Wl @0, Wr @WOFF)
__device__ __half g_wtl[2 * WOFF];   // transposed weights, fp16 lo
__device__ int    g_deg[NN];
__device__ int    g_rowptr[NN + 1];
__device__ int    g_cursor[NN];
__device__ int    g_csrc[ET];
__device__ int    g_bsum[128];
__device__ int    g_boff[128];
__device__ float  g_sum[GG * 256];
__device__ float  g_sq[GG * 256];
__device__ float  g_cs[GG * 256];
__device__ float  g_ct[GG * 256];
__device__ float  g_cnt[GG];
__device__ float  g_feat[GG * 16];

// ---------------- helpers ----------------------------------------------------
__device__ __forceinline__ void split_h(float v, __half& h, __half& l) {
    h = __float2half_rn(v);
    l = __float2half_rn(v - __half2float(h));
}
__device__ __forceinline__ float lrelu(float m) {
    return m > 0.f ? m : 0.2f * m;
}
__device__ __forceinline__ uint32_t smem_u32(const void* p) {
    uint32_t a;
    asm("{ .reg .u64 t; cvta.to.shared.u64 t, %1; cvt.u32.u64 %0, t; }"
        : "=r"(a) : "l"(p));
    return a;
}
__device__ __forceinline__ void cp16(uint32_t dst, const void* src, int sz) {
    asm volatile("cp.async.ca.shared.global [%0], [%1], 16, %2;"
                 :: "r"(dst), "l"(src), "r"(sz));
}
__device__ __forceinline__ void cp_commit() {
    asm volatile("cp.async.commit_group;" ::: "memory");
}
__device__ __forceinline__ void mma16816(float* c, const uint32_t* a, const uint32_t* b) {
    asm volatile(
        "mma.sync.aligned.m16n8k16.row.col.f32.f16.f16.f32 "
        "{%0,%1,%2,%3}, {%4,%5,%6,%7}, {%8,%9}, {%0,%1,%2,%3};"
        : "+f"(c[0]), "+f"(c[1]), "+f"(c[2]), "+f"(c[3])
        : "r"(a[0]), "r"(a[1]), "r"(a[2]), "r"(a[3]), "r"(b[0]), "r"(b[1]));
}

// convert fp32 buffer -> g_ah/g_al (float4 -> 2x half2 each)
__global__ void k_cvt(const float* __restrict__ src, int nf4) {
    int i = blockIdx.x * blockDim.x + threadIdx.x;
    if (i < nf4) {
        float4 v = ((const float4*)src)[i];
        __half h0, h1, h2, h3, l0, l1, l2, l3;
        split_h(v.x, h0, l0); split_h(v.y, h1, l1);
        split_h(v.z, h2, l2); split_h(v.w, h3, l3);
        ((__half2*)g_ah)[i * 2]     = __halves2half2(h0, h1);
        ((__half2*)g_ah)[i * 2 + 1] = __halves2half2(h2, h3);
        ((__half2*)g_al)[i * 2]     = __halves2half2(l0, l1);
        ((__half2*)g_al)[i * 2 + 1] = __halves2half2(l2, l3);
    }
}

// transpose + hi/lo split both weight matrices of a layer
__global__ void k_cvtB2(const float* __restrict__ W0, const float* __restrict__ W1,
                        int K, int Nn) {
    int total = K * Nn;
    int i = blockIdx.x * blockDim.x + threadIdx.x;
    if (i < 2 * total) {
        int m = i >= total;
        int j = i - m * total;
        int k = j / Nn, n = j - k * Nn;
        float v = (m ? W1 : W0)[j];
        __half h, l;
        split_h(v, h, l);
        int dst = m * WOFF + n * K + k;
        g_wth[dst] = h;
        g_wtl[dst] = l;
    }
}

// ---------------- CSR build --------------------------------------------------
__global__ void k_init_deg() {
    int i = blockIdx.x * blockDim.x + threadIdx.x;
    if (i < NN) g_deg[i] = 1;  // self loop
}

__global__ void k_count(const int* __restrict__ ei) {
    int e = blockIdx.x * blockDim.x + threadIdx.x;
    if (e < EE) atomicAdd(&g_deg[ei[EE + e]], 1);
}

__global__ void k_scan_blk() {
    __shared__ int wsum[16];
    const int b = blockIdx.x, t = threadIdx.x, lane = t & 31, w = t >> 5;
    const int i = b * SCAN_B + t;
    int v = (i < NN) ? g_deg[i] : 0;
    int s = v;
#pragma unroll
    for (int o = 1; o < 32; o <<= 1) {
        int u = __shfl_up_sync(0xffffffffu, s, o);
        if (lane >= o) s += u;
    }
    if (lane == 31) wsum[w] = s;
    __syncthreads();
    if (w == 0) {
        int ws = (lane < 16) ? wsum[lane] : 0;
        int t2 = ws;
#pragma unroll
        for (int o = 1; o < 32; o <<= 1) {
            int u = __shfl_up_sync(0xffffffffu, t2, o);
            if (lane >= o) t2 += u;
        }
        if (lane < 16) wsum[lane] = t2 - ws;
    }
    __syncthreads();
    if (i < NN) g_rowptr[i] = wsum[w] + s - v;
    if (t == SCAN_B - 1) g_bsum[b] = wsum[15] + s;
}

__global__ void k_scan_top() {
    __shared__ int wsum[4];
    const int t = threadIdx.x, lane = t & 31, w = t >> 5;
    int v = (t < NSCAN) ? g_bsum[t] : 0;
    int s = v;
#pragma unroll
    for (int o = 1; o < 32; o <<= 1) {
        int u = __shfl_up_sync(0xffffffffu, s, o);
        if (lane >= o) s += u;
    }
    if (lane == 31) wsum[w] = s;
    __syncthreads();
    if (w == 0) {
        int ws = (lane < 4) ? wsum[lane] : 0;
        int t2 = ws;
#pragma unroll
        for (int o = 1; o < 32; o <<= 1) {
            int u = __shfl_up_sync(0xffffffffu, t2, o);
            if (lane >= o) t2 += u;
        }
        if (lane < 4) wsum[lane] = t2 - ws;
    }
    __syncthreads();
    if (t < NSCAN) g_boff[t] = wsum[w] + s - v;
    if (t == 127) g_rowptr[NN] = wsum[3] + s;
}

__global__ void k_scan_add() {
    int i = blockIdx.x * blockDim.x + threadIdx.x;
    if (i < NN) {
        int r = g_rowptr[i] + g_boff[i / SCAN_B];
        g_rowptr[i] = r;
        g_cursor[i] = r;
    }
}

__global__ void k_scatter(const int* __restrict__ ei) {
    int e = blockIdx.x * blockDim.x + threadIdx.x;
    if (e < ET) {
        int s, d;
        if (e < EE) { s = ei[e]; d = ei[EE + e]; }
        else        { s = d = e - EE; }
        int p = atomicAdd(&g_cursor[d], 1);
        g_csrc[p] = s;
    }
}

__global__ void k_count_batch(const int* __restrict__ batch) {
    int i = blockIdx.x * blockDim.x + threadIdx.x;
    if (i < NN) atomicAdd(&g_cnt[batch[i]], 1.0f);
}

// ---------------- HMMA fp16-3x GEMM: cp.async double-buffered pipeline -------
// C ~= Ah*Bh + Ah*Bl + Al*Bh (fp32 accum). A pre-split in g_ah/g_al,
// B pre-split+transposed in g_wth/g_wtl. Tile 128x64, K-chunk 16,
// 256 thr (8 warps = 4Mx2N), blockIdx.z: dual (bias, C).
#define APAD 24  // 48B rows: 16B-aligned cp.async dsts; frag banks conflict-free

__global__ void __launch_bounds__(256)
k_gemm_mma(const __half* __restrict__ Ahg, const __half* __restrict__ Alg,
           const float* __restrict__ bias0, const float* __restrict__ bias1,
           float* __restrict__ C0, float* __restrict__ C1,
           int M, int K, int Nn) {
    const float* bias = blockIdx.z ? bias1 : bias0;
    float*       C    = blockIdx.z ? C1 : C0;
    const __half* WTh = g_wth + (blockIdx.z ? WOFF : 0);
    const __half* WTl = g_wtl + (blockIdx.z ? WOFF : 0);

    __shared__ alignas(16) __half Ahs[2][128 * APAD], Als[2][128 * APAD];
    __shared__ alignas(16) __half Bhs[2][64 * APAD],  Bls[2][64 * APAD];

    const int tid = threadIdx.x, lane = tid & 31, wid = tid >> 5;
    const int row0 = blockIdx.y * 128, col0 = blockIdx.x * 64;
    const int wm = wid >> 1, wn = wid & 1;
    const int fr = lane >> 2, fc = (lane & 3) * 2;

    // cp.async fill mappings
    const int ar = tid >> 1, ao = (tid & 1) * 8;      // A: row ar, 8 halves at k=ao
    const int bt = tid & 127, bn = bt >> 1, bko = (bt & 1) * 8;  // B: row bn, 8 halves
    const __half* Wsel = (tid < 128) ? WTh : WTl;
    const int asz = (row0 + ar < M) ? 16 : 0;         // zero-fill OOB rows

    float acc[2][4][4];
#pragma unroll
    for (int i = 0; i < 2; i++)
#pragma unroll
        for (int j = 0; j < 4; j++)
#pragma unroll
            for (int q = 0; q < 4; q++) acc[i][j][q] = 0.f;

    const int nkc = K >> 4;

#define LOAD_CHUNK(kc, buf)                                                        \
    do {                                                                           \
        size_t aoff = (size_t)(row0 + ar) * K + (kc) * 16 + ao;                    \
        cp16(smem_u32(&Ahs[buf][ar * APAD + ao]), Ahg + aoff, asz);                \
        cp16(smem_u32(&Als[buf][ar * APAD + ao]), Alg + aoff, asz);                \
        __half* bd = (tid < 128) ? &Bhs[buf][bn * APAD + bko]                      \
                                 : &Bls[buf][bn * APAD + bko];                     \
        cp16(smem_u32(bd), Wsel + (size_t)(col0 + bn) * K + (kc) * 16 + bko, 16);  \
    } while (0)

    LOAD_CHUNK(0, 0);
    cp_commit();

    for (int kc = 0; kc < nkc; kc++) {
        const int cur = kc & 1;
        if (kc + 1 < nkc) {
            LOAD_CHUNK(kc + 1, cur ^ 1);
            cp_commit();
            asm volatile("cp.async.wait_group 1;" ::: "memory");
        } else {
            asm volatile("cp.async.wait_group 0;" ::: "memory");
        }
        __syncthreads();

        uint32_t ah[2][4], al[2][4], bh[4][2], bl[4][2];
#pragma unroll
        for (int ma = 0; ma < 2; ma++) {
            int r = wm * 32 + ma * 16 + fr;
            ah[ma][0] = *(const uint32_t*)&Ahs[cur][r * APAD + fc];
            ah[ma][1] = *(const uint32_t*)&Ahs[cur][(r + 8) * APAD + fc];
            ah[ma][2] = *(const uint32_t*)&Ahs[cur][r * APAD + fc + 8];
            ah[ma][3] = *(const uint32_t*)&Ahs[cur][(r + 8) * APAD + fc + 8];
            al[ma][0] = *(const uint32_t*)&Als[cur][r * APAD + fc];
            al[ma][1] = *(const uint32_t*)&Als[cur][(r + 8) * APAD + fc];
            al[ma][2] = *(const uint32_t*)&Als[cur][r * APAD + fc + 8];
            al[ma][3] = *(const uint32_t*)&Als[cur][(r + 8) * APAD + fc + 8];
        }
#pragma unroll
        for (int na = 0; na < 4; na++) {
            int cn = wn * 32 + na * 8 + fr;
            bh[na][0] = *(const uint32_t*)&Bhs[cur][cn * APAD + fc];
            bh[na][1] = *(const uint32_t*)&Bhs[cur][cn * APAD + fc + 8];
            bl[na][0] = *(const uint32_t*)&Bls[cur][cn * APAD + fc];
            bl[na][1] = *(const uint32_t*)&Bls[cur][cn * APAD + fc + 8];
        }
#pragma unroll
        for (int ma = 0; ma < 2; ma++)
#pragma unroll
            for (int na = 0; na < 4; na++) {
                mma16816(acc[ma][na], ah[ma], bh[na]);
                mma16816(acc[ma][na], ah[ma], bl[na]);
                mma16816(acc[ma][na], al[ma], bh[na]);
            }
        __syncthreads();  // all reads of buf `cur` done before it is refilled
    }
#undef LOAD_CHUNK

#pragma unroll
    for (int ma = 0; ma < 2; ma++)
#pragma unroll
        for (int na = 0; na < 4; na++) {
            int r = row0 + wm * 32 + ma * 16 + fr;
            int c = col0 + wn * 32 + na * 8 + fc;
            float2 bb = *(const float2*)&bias[c];
            if (r < M)
                *(float2*)&C[(size_t)r * Nn + c] =
                    make_float2(acc[ma][na][0] + bb.x, acc[ma][na][1] + bb.y);
            if (r + 8 < M)
                *(float2*)&C[(size_t)(r + 8) * Nn + c] =
                    make_float2(acc[ma][na][2] + bb.x, acc[ma][na][3] + bb.y);
        }
}

// ---------------- GATv2 attention: head-aligned lanes (R12 measured-best) ----
template <int D, bool CONCAT>
__global__ void k_attn(const float* __restrict__ xl, const float* __restrict__ xr,
                       const float* __restrict__ att, const float* __restrict__ bias,
                       float* __restrict__ out) {
    constexpr int HD = 4 * D;
    constexpr int NW = HD / 32;
    const int node = blockIdx.x;
    const int tid = threadIdx.x, lane = tid & 31, w = tid >> 5;
    __shared__ float sden[NW][4];
    __shared__ float sacc[NW][HD];
    __shared__ float sinv[4];

    const int beg = g_rowptr[node], end = g_rowptr[node + 1];
    const float* xrp = xr + (size_t)node * HD;

    if (D == 64) {
        float4 rx0 = *(const float4*)&xrp[4 * lane];
        float4 rx1 = *(const float4*)&xrp[128 + 4 * lane];
        float4 ra0 = *(const float4*)&att[4 * lane];
        float4 ra1 = *(const float4*)&att[128 + 4 * lane];
        float acc0[4] = {0.f, 0.f, 0.f, 0.f}, acc1[4] = {0.f, 0.f, 0.f, 0.f};
        float dena = 0.f, denb = 0.f;
        for (int e = beg + w; e < end; e += NW) {
            const float* xs = xl + (size_t)g_csrc[e] * 256;
            float4 x0 = *(const float4*)&xs[4 * lane];
            float4 x1 = *(const float4*)&xs[128 + 4 * lane];
            float pa = lrelu(x0.x + rx0.x) * ra0.x;
            pa = fmaf(lrelu(x0.y + rx0.y), ra0.y, pa);
            pa = fmaf(lrelu(x0.z + rx0.z), ra0.z, pa);
            pa = fmaf(lrelu(x0.w + rx0.w), ra0.w, pa);
            float pb = lrelu(x1.x + rx1.x) * ra1.x;
            pb = fmaf(lrelu(x1.y + rx1.y), ra1.y, pb);
            pb = fmaf(lrelu(x1.z + rx1.z), ra1.z, pb);
            pb = fmaf(lrelu(x1.w + rx1.w), ra1.w, pb);
#pragma unroll
            for (int o = 8; o; o >>= 1) {
                pa += __shfl_xor_sync(0xffffffffu, pa, o);
                pb += __shfl_xor_sync(0xffffffffu, pb, o);
            }
            float wa = __expf(pa), wb = __expf(pb);
            dena += wa; denb += wb;
            acc0[0] = fmaf(wa, x0.x, acc0[0]); acc0[1] = fmaf(wa, x0.y, acc0[1]);
            acc0[2] = fmaf(wa, x0.z, acc0[2]); acc0[3] = fmaf(wa, x0.w, acc0[3]);
            acc1[0] = fmaf(wb, x1.x, acc1[0]); acc1[1] = fmaf(wb, x1.y, acc1[1]);
            acc1[2] = fmaf(wb, x1.z, acc1[2]); acc1[3] = fmaf(wb, x1.w, acc1[3]);
        }
        *(float4*)&sacc[w][4 * lane] = make_float4(acc0[0], acc0[1], acc0[2], acc0[3]);
        *(float4*)&sacc[w][128 + 4 * lane] = make_float4(acc1[0], acc1[1], acc1[2], acc1[3]);
        if (lane == 0)  { sden[w][0] = dena; sden[w][2] = denb; }
        if (lane == 16) { sden[w][1] = dena; sden[w][3] = denb; }
    } else if (D == 32) {
        float4 rx = *(const float4*)&xrp[4 * lane];
        float4 ra = *(const float4*)&att[4 * lane];
        float acc[4] = {0.f, 0.f, 0.f, 0.f};
        float den = 0.f;
        for (int e = beg + w; e < end; e += NW) {
            const float* xs = xl + (size_t)g_csrc[e] * 128;
            float4 x0 = *(const float4*)&xs[4 * lane];
            float p = lrelu(x0.x + rx.x) * ra.x;
            p = fmaf(lrelu(x0.y + rx.y), ra.y, p);
            p = fmaf(lrelu(x0.z + rx.z), ra.z, p);
            p = fmaf(lrelu(x0.w + rx.w), ra.w, p);
#pragma unroll
            for (int o = 4; o; o >>= 1) p += __shfl_xor_sync(0xffffffffu, p, o);
            float wg = __expf(p);
            den += wg;
            acc[0] = fmaf(wg, x0.x, acc[0]); acc[1] = fmaf(wg, x0.y, acc[1]);
            acc[2] = fmaf(wg, x0.z, acc[2]); acc[3] = fmaf(wg, x0.w, acc[3]);
        }
        *(float4*)&sacc[w][4 * lane] = make_float4(acc[0], acc[1], acc[2], acc[3]);
        if ((lane & 7) == 0) sden[w][lane >> 3] = den;
    } else {
        float2 rx = *(const float2*)&xrp[2 * lane];
        float2 ra = *(const float2*)&att[2 * lane];
        float acc[2] = {0.f, 0.f};
        float den = 0.f;
        for (int e = beg + w; e < end; e += NW) {
            const float* xs = xl + (size_t)g_csrc[e] * 64;
            float2 x0 = *(const float2*)&xs[2 * lane];
            float p = lrelu(x0.x + rx.x) * ra.x;
            p = fmaf(lrelu(x0.y + rx.y), ra.y, p);
#pragma unroll
            for (int o = 4; o; o >>= 1) p += __shfl_xor_sync(0xffffffffu, p, o);
            float wg = __expf(p);
            den += wg;
            acc[0] = fmaf(wg, x0.x, acc[0]); acc[1] = fmaf(wg, x0.y, acc[1]);
        }
        *(float2*)&sacc[w][2 * lane] = make_float2(acc[0], acc[1]);
        if ((lane & 7) == 0) sden[w][lane >> 3] = den;
    }
    __syncthreads();

    if (tid < 4) {
        float dt = 0.f;
#pragma unroll
        for (int i = 0; i < NW; i++) dt += sden[i][tid];
        sinv[tid] = 1.f / (dt + 1e-16f);
    }
    __syncthreads();

    {
        const int c = tid, h = c / D;
        float a = 0.f;
#pragma unroll
        for (int i = 0; i < NW; i++) a += sacc[i][c];
        float r = a * sinv[h];
        if (CONCAT) {
            out[(size_t)node * HD + c] = r + bias[c];
        } else {
            __syncthreads();
            sacc[0][c] = r;
        }
    }
    if (!CONCAT) {
        __syncthreads();
        if (tid < D)
            out[(size_t)node * D + tid] =
                0.25f * (sacc[0][tid] + sacc[0][D + tid] + sacc[0][2 * D + tid] + sacc[0][3 * D + tid]) + bias[tid];
    }
}

// ---------------- GraphNorm (scalar reduce: 838-measured-best form) ----------
#define GN_CHUNK 64
__global__ void k_gn_reduce(const float* __restrict__ x, const int* __restrict__ batch,
                            int F) {
    __shared__ int sb[GN_CHUNK];
    const int tid = threadIdx.x;
    const int R = 256 / F < 1 ? 1 : 256 / F;
    const int f = tid % F;
    const int r = tid / F;
    const int n0 = blockIdx.x * GN_CHUNK;
    if (tid < GN_CHUNK) sb[tid] = (n0 + tid < NN) ? batch[n0 + tid] : -1;
    __syncthreads();
    if (r >= R) return;
    float s = 0.f, q = 0.f;
    int cg = -1;
    for (int i = r; i < GN_CHUNK && n0 + i < NN; i += R) {
        int g = sb[i];
        if (g != cg) {
            if (cg >= 0) {
                atomicAdd(&g_sum[cg * F + f], s);
                atomicAdd(&g_sq[cg * F + f], q);
            }
            s = 0.f; q = 0.f; cg = g;
        }
        float v = x[(size_t)(n0 + i) * F + f];
        s += v;
        q = fmaf(v, v, q);
    }
    if (cg >= 0) {
        atomicAdd(&g_sum[cg * F + f], s);
        atomicAdd(&g_sq[cg * F + f], q);
    }
}

__global__ void k_gn_coef(const float* __restrict__ w, const float* __restrict__ b,
                          const float* __restrict__ a, int F) {
    int i = blockIdx.x * blockDim.x + threadIdx.x;
    if (i < GG * F) {
        int f = i % F;
        float c = fmaxf(g_cnt[i / F], 1.0f);
        float mean = g_sum[i] / c;
        float av = a[f];
        float var = g_sq[i] / c + mean * mean * (av * av - 2.f * av);
        var = fmaxf(var, 0.f);
        float s = w[f] * rsqrtf(var + 1e-5f);
        g_cs[i] = s;
        g_ct[i] = b[f] - s * av * mean;
        g_sum[i] = 0.f;
        g_sq[i] = 0.f;
    }
}

// apply + ReLU, emit fp16 hi/lo directly for the next GEMM's A operand
__global__ void k_gn_apply_half(const float* __restrict__ x, const int* __restrict__ batch,
                                int F) {
    int Fq = F >> 2;
    int idx = blockIdx.x * blockDim.x + threadIdx.x;
    if (idx < NN * Fq) {
        int n = idx / Fq, f4 = (idx - n * Fq) * 4;
        int g = batch[n];
        float4 xv = *(const float4*)&x[(size_t)n * F + f4];
        float4 s = *(const float4*)&g_cs[g * F + f4];
        float4 t = *(const float4*)&g_ct[g * F + f4];
        float y0 = fmaxf(fmaf(s.x, xv.x, t.x), 0.f);
        float y1 = fmaxf(fmaf(s.y, xv.y, t.y), 0.f);
        float y2 = fmaxf(fmaf(s.z, xv.z, t.z), 0.f);
        float y3 = fmaxf(fmaf(s.w, xv.w, t.w), 0.f);
        __half h0, h1, h2, h3, l0, l1, l2, l3;
        split_h(y0, h0, l0); split_h(y1, h1, l1);
        split_h(y2, h2, l2); split_h(y3, h3, l3);
        size_t o2 = ((size_t)n * F + f4) >> 1;
        ((__half2*)g_ah)[o2]     = __halves2half2(h0, h1);
        ((__half2*)g_ah)[o2 + 1] = __halves2half2(h2, h3);
        ((__half2*)g_al)[o2]     = __halves2half2(l0, l1);
        ((__half2*)g_al)[o2 + 1] = __halves2half2(l2, l3);
    }
}

// apply + ReLU + pool (layer 3, F=16; output feeds only the pool)
__global__ void k_gn_apply_pool(const float* __restrict__ x, const int* __restrict__ batch) {
    const int F = 16, Fq = 4;
    int idx = blockIdx.x * blockDim.x + threadIdx.x;
    if (idx < NN * Fq) {
        int n = idx / Fq, f4 = (idx - n * Fq) * 4;
        int g = batch[n];
        float4 xv = *(const float4*)&x[(size_t)n * F + f4];
        float4 s = *(const float4*)&g_cs[g * F + f4];
        float4 t = *(const float4*)&g_ct[g * F + f4];
        atomicAdd(&g_feat[g * 16 + f4 + 0], fmaxf(fmaf(s.x, xv.x, t.x), 0.f));
        atomicAdd(&g_feat[g * 16 + f4 + 1], fmaxf(fmaf(s.y, xv.y, t.y), 0.f));
        atomicAdd(&g_feat[g * 16 + f4 + 2], fmaxf(fmaf(s.z, xv.z, t.z), 0.f));
        atomicAdd(&g_feat[g * 16 + f4 + 3], fmaxf(fmaf(s.w, xv.w, t.w), 0.f));
    }
}

// ---------------- classifier head ---------------------------------------------
__global__ void k_head(const float* __restrict__ linW, const float* __restrict__ linB,
                       float* __restrict__ out) {
    __shared__ float sf[GG * 16];
    int tid = threadIdx.x;
    if (tid < GG * 16) {
        int g = tid / 16;
        float v = g_feat[tid] / fmaxf(g_cnt[g], 1.0f);
        sf[tid] = v;
        out[GG * 4 + tid] = v;
        g_feat[tid] = 0.f;
    }
    if (tid < GG) g_cnt[tid] = 0.f;
    __syncthreads();
    if (tid < GG * 4) {
        int g = tid >> 2, c = tid & 3;
        float s = linB[c];
#pragma unroll
        for (int f = 0; f < 16; f++) s = fmaf(sf[g * 16 + f], linW[f * 4 + c], s);
        out[g * 4 + c] = s;
    }
}

// ---------------- host orchestration ------------------------------------------
static void run_gemm2(const float* bias0, const float* bias1,
                      float* C0, float* C1, int M, int K, int Nn) {
    __half *ah, *al;
    cudaGetSymbolAddress((void**)&ah, g_ah);
    cudaGetSymbolAddress((void**)&al, g_al);
    dim3 grid(Nn / 64, (M + 127) / 128, 2);
    k_gemm_mma<<<grid, 256>>>(ah, al, bias0, bias1, C0, C1, M, K, Nn);
}

extern "C" void kernel_launch(void* const* d_in, const int* in_sizes, int n_in,
                              void* d_out, int out_size) {
    const float* x     = (const float*)d_in[0];
    const int*   ei    = (const int*)d_in[1];
    const int*   batch = (const int*)d_in[2];
    const float* Wl1 = (const float*)d_in[3],  *bl1 = (const float*)d_in[4];
    const float* Wr1 = (const float*)d_in[5],  *br1 = (const float*)d_in[6];
    const float* att1 = (const float*)d_in[7], *bias1 = (const float*)d_in[8];
    const float* gw1 = (const float*)d_in[9],  *gb1 = (const float*)d_in[10], *ga1 = (const float*)d_in[11];
    const float* Wl2 = (const float*)d_in[12], *bl2 = (const float*)d_in[13];
    const float* Wr2 = (const float*)d_in[14], *br2 = (const float*)d_in[15];
    const float* att2 = (const float*)d_in[16], *bias2 = (const float*)d_in[17];
    const float* gw2 = (const float*)d_in[18], *gb2 = (const float*)d_in[19], *ga2 = (const float*)d_in[20];
    const float* Wl3 = (const float*)d_in[21], *bl3 = (const float*)d_in[22];
    const float* Wr3 = (const float*)d_in[23], *br3 = (const float*)d_in[24];
    const float* att3 = (const float*)d_in[25], *bias3 = (const float*)d_in[26];
    const float* gw3 = (const float*)d_in[27], *gb3 = (const float*)d_in[28], *ga3 = (const float*)d_in[29];
    const float* linW = (const float*)d_in[30], *linB = (const float*)d_in[31];

    float *xl, *xr, *b1, *b2;
    cudaGetSymbolAddress((void**)&xl, g_xl);
    cudaGetSymbolAddress((void**)&xr, g_xr);
    cudaGetSymbolAddress((void**)&b1, g_b1);
    cudaGetSymbolAddress((void**)&b2, g_b2);

    // launches 0-2
    k_cvt<<<(NN * 32 + 255) / 256, 256>>>(x, NN * 32);
    k_cvtB2<<<(2 * 128 * 256 + 255) / 256, 256>>>(Wl1, Wr1, 128, 256);
    k_init_deg<<<(NN + 255) / 256, 256>>>();

    // launch 3: layer-1 dual GEMM (profiled position)
    run_gemm2(bl1, br1, xl, xr, NN, 128, 256);

    // CSR build
    k_count<<<(EE + 255) / 256, 256>>>(ei);
    k_scan_blk<<<NSCAN, SCAN_B>>>();
    k_scan_top<<<1, 128>>>();
    k_scan_add<<<(NN + 255) / 256, 256>>>();
    k_scatter<<<(ET + 255) / 256, 256>>>(ei);
    k_count_batch<<<(NN + 255) / 256, 256>>>(batch);

    // ---- layer 1: 128 -> 4x64 concat (256) ----
    k_attn<64, true><<<NN, 256>>>(xl, xr, att1, bias1, b1);
    k_gn_reduce<<<(NN + GN_CHUNK - 1) / GN_CHUNK, 256>>>(b1, batch, 256);
    k_gn_coef<<<(GG * 256 + 255) / 256, 256>>>(gw1, gb1, ga1, 256);
    k_gn_apply_half<<<(NN * 64 + 255) / 256, 256>>>(b1, batch, 256);

    // ---- layer 2: 256 -> 4x32 concat (128) ----
    k_cvtB2<<<(2 * 256 * 128 + 255) / 256, 256>>>(Wl2, Wr2, 256, 128);
    run_gemm2(bl2, br2, xl, xr, NN, 256, 128);
    k_attn<32, true><<<NN, 128>>>(xl, xr, att2, bias2, b2);
    k_gn_reduce<<<(NN + GN_CHUNK - 1) / GN_CHUNK, 256>>>(b2, batch, 128);
    k_gn_coef<<<(GG * 128 + 255) / 256, 256>>>(gw2, gb2, ga2, 128);
    k_gn_apply_half<<<(NN * 32 + 255) / 256, 256>>>(b2, batch, 128);

    // ---- layer 3: 128 -> 4x16 averaged (16) ----
    k_cvtB2<<<(2 * 128 * 64 + 255) / 256, 256>>>(Wl3, Wr3, 128, 64);
    run_gemm2(bl3, br3, xl, xr, NN, 128, 64);
    k_attn<16, false><<<NN, 64>>>(xl, xr, att3, bias3, b1);
    k_gn_reduce<<<(NN + GN_CHUNK - 1) / GN_CHUNK, 256>>>(b1, batch, 16);
    k_gn_coef<<<(GG * 16 + 255) / 256, 256>>>(gw3, gb3, ga3, 16);
    k_gn_apply_pool<<<(NN * 4 + 255) / 256, 256>>>(b1, batch);

    // ---- head ----
    k_head<<<1, 512>>>(linW, linB, (float*)d_out);
}

// round 15
// speedup vs baseline: 1.1587x; 1.0509x over previous
#include <cuda_runtime.h>
#include <cuda_fp16.h>
#include <math.h>
#include <stdint.h>

#define NN 50000
#define EE 800000
#define ET (EE + NN)
#define GG 32
#define SCAN_B 512
#define NSCAN ((NN + SCAN_B - 1) / SCAN_B)   // 98
#define WOFF 32768

// ---------------- scratch (device globals; no allocation allowed) ----------
__device__ float  g_xl[NN * 256];
__device__ float  g_xr[NN * 256];
__device__ float  g_b1[NN * 256];
__device__ float  g_b2[NN * 256];
__device__ __half g_ah[NN * 256];     // GEMM A operand, fp16 hi
__device__ __half g_al[NN * 256];     // GEMM A operand, fp16 lo
__device__ __half g_wth[5 * WOFF];    // all transposed weights, fp16 hi
__device__ __half g_wtl[5 * WOFF];    // all transposed weights, fp16 lo
__device__ int    g_deg[NN];
__device__ int    g_rowptr[NN + 1];
__device__ int    g_cursor[NN];
__device__ int    g_csrc[ET];
__device__ int    g_bsum[128];
__device__ int    g_boff[128];
__device__ float  g_sum[GG * 256];
__device__ float  g_sq[GG * 256];
__device__ float  g_cs[GG * 256];
__device__ float  g_ct[GG * 256];
__device__ float  g_cnt[GG];
__device__ float  g_feat[GG * 16];

// ---------------- helpers ----------------------------------------------------
__device__ __forceinline__ void split_h(float v, __half& h, __half& l) {
    h = __float2half_rn(v);
    l = __float2half_rn(v - __half2float(h));
}
__device__ __forceinline__ float lrelu(float m) {
    return m > 0.f ? m : 0.2f * m;
}
__device__ __forceinline__ uint32_t smem_u32(const void* p) {
    uint32_t a;
    asm("{ .reg .u64 t; cvta.to.shared.u64 t, %1; cvt.u32.u64 %0, t; }"
        : "=r"(a) : "l"(p));
    return a;
}
__device__ __forceinline__ void cp16(uint32_t dst, const void* src, int sz) {
    asm volatile("cp.async.ca.shared.global [%0], [%1], 16, %2;"
                 :: "r"(dst), "l"(src), "r"(sz));
}
__device__ __forceinline__ void cp_commit() {
    asm volatile("cp.async.commit_group;" ::: "memory");
}
__device__ __forceinline__ void mma16816(float* c, const uint32_t* a, const uint32_t* b) {
    asm volatile(
        "mma.sync.aligned.m16n8k16.row.col.f32.f16.f16.f32 "
        "{%0,%1,%2,%3}, {%4,%5,%6,%7}, {%8,%9}, {%0,%1,%2,%3};"
        : "+f"(c[0]), "+f"(c[1]), "+f"(c[2]), "+f"(c[3])
        : "r"(a[0]), "r"(a[1]), "r"(a[2]), "r"(a[3]), "r"(b[0]), "r"(b[1]));
}

// convert fp32 buffer -> g_ah/g_al
__global__ void k_cvt(const float* __restrict__ src, int nf4) {
    int i = blockIdx.x * blockDim.x + threadIdx.x;
    if (i < nf4) {
        float4 v = ((const float4*)src)[i];
        __half h0, h1, h2, h3, l0, l1, l2, l3;
        split_h(v.x, h0, l0); split_h(v.y, h1, l1);
        split_h(v.z, h2, l2); split_h(v.w, h3, l3);
        ((__half2*)g_ah)[i * 2]     = __halves2half2(h0, h1);
        ((__half2*)g_ah)[i * 2 + 1] = __halves2half2(h2, h3);
        ((__half2*)g_al)[i * 2]     = __halves2half2(l0, l1);
        ((__half2*)g_al)[i * 2 + 1] = __halves2half2(l2, l3);
    }
}

// transpose + hi/lo split ALL six weight matrices in one launch.
// layout: Wl1@0, Wr1@WOFF, Wl2@2W, Wr2@3W, Wl3@4W, Wr3@4W+8192
__global__ void k_cvtB_all(const float* __restrict__ Wl1, const float* __restrict__ Wr1,
                           const float* __restrict__ Wl2, const float* __restrict__ Wr2,
                           const float* __restrict__ Wl3, const float* __restrict__ Wr3) {
    int i = blockIdx.x * blockDim.x + threadIdx.x;
    const float* src;
    int j, K, Nn, base;
    if (i < 32768)        { src = Wl1; j = i;          K = 128; Nn = 256; base = 0; }
    else if (i < 65536)   { src = Wr1; j = i - 32768;  K = 128; Nn = 256; base = WOFF; }
    else if (i < 98304)   { src = Wl2; j = i - 65536;  K = 256; Nn = 128; base = 2 * WOFF; }
    else if (i < 131072)  { src = Wr2; j = i - 98304;  K = 256; Nn = 128; base = 3 * WOFF; }
    else if (i < 139264)  { src = Wl3; j = i - 131072; K = 128; Nn = 64;  base = 4 * WOFF; }
    else if (i < 147456)  { src = Wr3; j = i - 139264; K = 128; Nn = 64;  base = 4 * WOFF + 8192; }
    else return;
    int k = j / Nn, n = j - k * Nn;
    float v = src[j];
    __half h, l;
    split_h(v, h, l);
    int dst = base + n * K + k;
    g_wth[dst] = h;
    g_wtl[dst] = l;
}

// ---------------- CSR build --------------------------------------------------
__global__ void k_init_deg() {
    int i = blockIdx.x * blockDim.x + threadIdx.x;
    if (i < NN) g_deg[i] = 1;  // self loop
}

__global__ void k_count(const int* __restrict__ ei) {
    int e = blockIdx.x * blockDim.x + threadIdx.x;
    if (e < EE) atomicAdd(&g_deg[ei[EE + e]], 1);
}

__global__ void k_scan_blk() {
    __shared__ int wsum[16];
    const int b = blockIdx.x, t = threadIdx.x, lane = t & 31, w = t >> 5;
    const int i = b * SCAN_B + t;
    int v = (i < NN) ? g_deg[i] : 0;
    int s = v;
#pragma unroll
    for (int o = 1; o < 32; o <<= 1) {
        int u = __shfl_up_sync(0xffffffffu, s, o);
        if (lane >= o) s += u;
    }
    if (lane == 31) wsum[w] = s;
    __syncthreads();
    if (w == 0) {
        int ws = (lane < 16) ? wsum[lane] : 0;
        int t2 = ws;
#pragma unroll
        for (int o = 1; o < 32; o <<= 1) {
            int u = __shfl_up_sync(0xffffffffu, t2, o);
            if (lane >= o) t2 += u;
        }
        if (lane < 16) wsum[lane] = t2 - ws;
    }
    __syncthreads();
    if (i < NN) g_rowptr[i] = wsum[w] + s - v;
    if (t == SCAN_B - 1) g_bsum[b] = wsum[15] + s;
}

__global__ void k_scan_top() {
    __shared__ int wsum[4];
    const int t = threadIdx.x, lane = t & 31, w = t >> 5;
    int v = (t < NSCAN) ? g_bsum[t] : 0;
    int s = v;
#pragma unroll
    for (int o = 1; o < 32; o <<= 1) {
        int u = __shfl_up_sync(0xffffffffu, s, o);
        if (lane >= o) s += u;
    }
    if (lane == 31) wsum[w] = s;
    __syncthreads();
    if (w == 0) {
        int ws = (lane < 4) ? wsum[lane] : 0;
        int t2 = ws;
#pragma unroll
        for (int o = 1; o < 32; o <<= 1) {
            int u = __shfl_up_sync(0xffffffffu, t2, o);
            if (lane >= o) t2 += u;
        }
        if (lane < 4) wsum[lane] = t2 - ws;
    }
    __syncthreads();
    if (t < NSCAN) g_boff[t] = wsum[w] + s - v;
    if (t == 127) g_rowptr[NN] = wsum[3] + s;
}

__global__ void k_scan_add() {
    int i = blockIdx.x * blockDim.x + threadIdx.x;
    if (i < NN) {
        int r = g_rowptr[i] + g_boff[i / SCAN_B];
        g_rowptr[i] = r;
        g_cursor[i] = r;
    }
}

__global__ void k_scatter(const int* __restrict__ ei) {
    int e = blockIdx.x * blockDim.x + threadIdx.x;
    if (e < ET) {
        int s, d;
        if (e < EE) { s = ei[e]; d = ei[EE + e]; }
        else        { s = d = e - EE; }
        int p = atomicAdd(&g_cursor[d], 1);
        g_csrc[p] = s;
    }
}

__global__ void k_count_batch(const int* __restrict__ batch) {
    int i = blockIdx.x * blockDim.x + threadIdx.x;
    if (i < NN) atomicAdd(&g_cnt[batch[i]], 1.0f);
}

// ---------------- HMMA fp16-3x GEMM: cp.async double-buffered (R14 best) -----
#define APAD 24

__global__ void __launch_bounds__(256)
k_gemm_mma(const __half* __restrict__ Ahg, const __half* __restrict__ Alg,
           const float* __restrict__ bias0, const float* __restrict__ bias1,
           float* __restrict__ C0, float* __restrict__ C1,
           int M, int K, int Nn, int wbase, int wdelta) {
    const float* bias = blockIdx.z ? bias1 : bias0;
    float*       C    = blockIdx.z ? C1 : C0;
    const __half* WTh = g_wth + wbase + (blockIdx.z ? wdelta : 0);
    const __half* WTl = g_wtl + wbase + (blockIdx.z ? wdelta : 0);

    __shared__ alignas(16) __half Ahs[2][128 * APAD], Als[2][128 * APAD];
    __shared__ alignas(16) __half Bhs[2][64 * APAD],  Bls[2][64 * APAD];

    const int tid = threadIdx.x, lane = tid & 31, wid = tid >> 5;
    const int row0 = blockIdx.y * 128, col0 = blockIdx.x * 64;
    const int wm = wid >> 1, wn = wid & 1;
    const int fr = lane >> 2, fc = (lane & 3) * 2;

    const int ar = tid >> 1, ao = (tid & 1) * 8;
    const int bt = tid & 127, bn = bt >> 1, bko = (bt & 1) * 8;
    const __half* Wsel = (tid < 128) ? WTh : WTl;
    const int asz = (row0 + ar < M) ? 16 : 0;

    float acc[2][4][4];
#pragma unroll
    for (int i = 0; i < 2; i++)
#pragma unroll
        for (int j = 0; j < 4; j++)
#pragma unroll
            for (int q = 0; q < 4; q++) acc[i][j][q] = 0.f;

    const int nkc = K >> 4;

#define LOAD_CHUNK(kc, buf)                                                        \
    do {                                                                           \
        size_t aoff = (size_t)(row0 + ar) * K + (kc) * 16 + ao;                    \
        cp16(smem_u32(&Ahs[buf][ar * APAD + ao]), Ahg + aoff, asz);                \
        cp16(smem_u32(&Als[buf][ar * APAD + ao]), Alg + aoff, asz);                \
        __half* bd = (tid < 128) ? &Bhs[buf][bn * APAD + bko]                      \
                                 : &Bls[buf][bn * APAD + bko];                     \
        cp16(smem_u32(bd), Wsel + (size_t)(col0 + bn) * K + (kc) * 16 + bko, 16);  \
    } while (0)

    LOAD_CHUNK(0, 0);
    cp_commit();

    for (int kc = 0; kc < nkc; kc++) {
        const int cur = kc & 1;
        if (kc + 1 < nkc) {
            LOAD_CHUNK(kc + 1, cur ^ 1);
            cp_commit();
            asm volatile("cp.async.wait_group 1;" ::: "memory");
        } else {
            asm volatile("cp.async.wait_group 0;" ::: "memory");
        }
        __syncthreads();

        uint32_t ah[2][4], al[2][4], bh[4][2], bl[4][2];
#pragma unroll
        for (int ma = 0; ma < 2; ma++) {
            int r = wm * 32 + ma * 16 + fr;
            ah[ma][0] = *(const uint32_t*)&Ahs[cur][r * APAD + fc];
            ah[ma][1] = *(const uint32_t*)&Ahs[cur][(r + 8) * APAD + fc];
            ah[ma][2] = *(const uint32_t*)&Ahs[cur][r * APAD + fc + 8];
            ah[ma][3] = *(const uint32_t*)&Ahs[cur][(r + 8) * APAD + fc + 8];
            al[ma][0] = *(const uint32_t*)&Als[cur][r * APAD + fc];
            al[ma][1] = *(const uint32_t*)&Als[cur][(r + 8) * APAD + fc];
            al[ma][2] = *(const uint32_t*)&Als[cur][r * APAD + fc + 8];
            al[ma][3] = *(const uint32_t*)&Als[cur][(r + 8) * APAD + fc + 8];
        }
#pragma unroll
        for (int na = 0; na < 4; na++) {
            int cn = wn * 32 + na * 8 + fr;
            bh[na][0] = *(const uint32_t*)&Bhs[cur][cn * APAD + fc];
            bh[na][1] = *(const uint32_t*)&Bhs[cur][cn * APAD + fc + 8];
            bl[na][0] = *(const uint32_t*)&Bls[cur][cn * APAD + fc];
            bl[na][1] = *(const uint32_t*)&Bls[cur][cn * APAD + fc + 8];
        }
#pragma unroll
        for (int ma = 0; ma < 2; ma++)
#pragma unroll
            for (int na = 0; na < 4; na++) {
                mma16816(acc[ma][na], ah[ma], bh[na]);
                mma16816(acc[ma][na], ah[ma], bl[na]);
                mma16816(acc[ma][na], al[ma], bh[na]);
            }
        __syncthreads();
    }
#undef LOAD_CHUNK

#pragma unroll
    for (int ma = 0; ma < 2; ma++)
#pragma unroll
        for (int na = 0; na < 4; na++) {
            int r = row0 + wm * 32 + ma * 16 + fr;
            int c = col0 + wn * 32 + na * 8 + fc;
            float2 bb = *(const float2*)&bias[c];
            if (r < M)
                *(float2*)&C[(size_t)r * Nn + c] =
                    make_float2(acc[ma][na][0] + bb.x, acc[ma][na][1] + bb.y);
            if (r + 8 < M)
                *(float2*)&C[(size_t)(r + 8) * Nn + c] =
                    make_float2(acc[ma][na][2] + bb.x, acc[ma][na][3] + bb.y);
        }
}

// ---------------- GATv2 attention: head-aligned lanes (R12 measured-best) ----
template <int D, bool CONCAT>
__global__ void k_attn(const float* __restrict__ xl, const float* __restrict__ xr,
                       const float* __restrict__ att, const float* __restrict__ bias,
                       float* __restrict__ out) {
    constexpr int HD = 4 * D;
    constexpr int NW = HD / 32;
    const int node = blockIdx.x;
    const int tid = threadIdx.x, lane = tid & 31, w = tid >> 5;
    __shared__ float sden[NW][4];
    __shared__ float sacc[NW][HD];
    __shared__ float sinv[4];

    const int beg = g_rowptr[node], end = g_rowptr[node + 1];
    const float* xrp = xr + (size_t)node * HD;

    if (D == 64) {
        float4 rx0 = *(const float4*)&xrp[4 * lane];
        float4 rx1 = *(const float4*)&xrp[128 + 4 * lane];
        float4 ra0 = *(const float4*)&att[4 * lane];
        float4 ra1 = *(const float4*)&att[128 + 4 * lane];
        float acc0[4] = {0.f, 0.f, 0.f, 0.f}, acc1[4] = {0.f, 0.f, 0.f, 0.f};
        float dena = 0.f, denb = 0.f;
        for (int e = beg + w; e < end; e += NW) {
            const float* xs = xl + (size_t)g_csrc[e] * 256;
            float4 x0 = *(const float4*)&xs[4 * lane];
            float4 x1 = *(const float4*)&xs[128 + 4 * lane];
            float pa = lrelu(x0.x + rx0.x) * ra0.x;
            pa = fmaf(lrelu(x0.y + rx0.y), ra0.y, pa);
            pa = fmaf(lrelu(x0.z + rx0.z), ra0.z, pa);
            pa = fmaf(lrelu(x0.w + rx0.w), ra0.w, pa);
            float pb = lrelu(x1.x + rx1.x) * ra1.x;
            pb = fmaf(lrelu(x1.y + rx1.y), ra1.y, pb);
            pb = fmaf(lrelu(x1.z + rx1.z), ra1.z, pb);
            pb = fmaf(lrelu(x1.w + rx1.w), ra1.w, pb);
#pragma unroll
            for (int o = 8; o; o >>= 1) {
                pa += __shfl_xor_sync(0xffffffffu, pa, o);
                pb += __shfl_xor_sync(0xffffffffu, pb, o);
            }
            float wa = __expf(pa), wb = __expf(pb);
            dena += wa; denb += wb;
            acc0[0] = fmaf(wa, x0.x, acc0[0]); acc0[1] = fmaf(wa, x0.y, acc0[1]);
            acc0[2] = fmaf(wa, x0.z, acc0[2]); acc0[3] = fmaf(wa, x0.w, acc0[3]);
            acc1[0] = fmaf(wb, x1.x, acc1[0]); acc1[1] = fmaf(wb, x1.y, acc1[1]);
            acc1[2] = fmaf(wb, x1.z, acc1[2]); acc1[3] = fmaf(wb, x1.w, acc1[3]);
        }
        *(float4*)&sacc[w][4 * lane] = make_float4(acc0[0], acc0[1], acc0[2], acc0[3]);
        *(float4*)&sacc[w][128 + 4 * lane] = make_float4(acc1[0], acc1[1], acc1[2], acc1[3]);
        if (lane == 0)  { sden[w][0] = dena; sden[w][2] = denb; }
        if (lane == 16) { sden[w][1] = dena; sden[w][3] = denb; }
    } else if (D == 32) {
        float4 rx = *(const float4*)&xrp[4 * lane];
        float4 ra = *(const float4*)&att[4 * lane];
        float acc[4] = {0.f, 0.f, 0.f, 0.f};
        float den = 0.f;
        for (int e = beg + w; e < end; e += NW) {
            const float* xs = xl + (size_t)g_csrc[e] * 128;
            float4 x0 = *(const float4*)&xs[4 * lane];
            float p = lrelu(x0.x + rx.x) * ra.x;
            p = fmaf(lrelu(x0.y + rx.y), ra.y, p);
            p = fmaf(lrelu(x0.z + rx.z), ra.z, p);
            p = fmaf(lrelu(x0.w + rx.w), ra.w, p);
#pragma unroll
            for (int o = 4; o; o >>= 1) p += __shfl_xor_sync(0xffffffffu, p, o);
            float wg = __expf(p);
            den += wg;
            acc[0] = fmaf(wg, x0.x, acc[0]); acc[1] = fmaf(wg, x0.y, acc[1]);
            acc[2] = fmaf(wg, x0.z, acc[2]); acc[3] = fmaf(wg, x0.w, acc[3]);
        }
        *(float4*)&sacc[w][4 * lane] = make_float4(acc[0], acc[1], acc[2], acc[3]);
        if ((lane & 7) == 0) sden[w][lane >> 3] = den;
    } else {
        float2 rx = *(const float2*)&xrp[2 * lane];
        float2 ra = *(const float2*)&att[2 * lane];
        float acc[2] = {0.f, 0.f};
        float den = 0.f;
        for (int e = beg + w; e < end; e += NW) {
            const float* xs = xl + (size_t)g_csrc[e] * 64;
            float2 x0 = *(const float2*)&xs[2 * lane];
            float p = lrelu(x0.x + rx.x) * ra.x;
            p = fmaf(lrelu(x0.y + rx.y), ra.y, p);
#pragma unroll
            for (int o = 4; o; o >>= 1) p += __shfl_xor_sync(0xffffffffu, p, o);
            float wg = __expf(p);
            den += wg;
            acc[0] = fmaf(wg, x0.x, acc[0]); acc[1] = fmaf(wg, x0.y, acc[1]);
        }
        *(float2*)&sacc[w][2 * lane] = make_float2(acc[0], acc[1]);
        if ((lane & 7) == 0) sden[w][lane >> 3] = den;
    }
    __syncthreads();

    if (tid < 4) {
        float dt = 0.f;
#pragma unroll
        for (int i = 0; i < NW; i++) dt += sden[i][tid];
        sinv[tid] = 1.f / (dt + 1e-16f);
    }
    __syncthreads();

    {
        const int c = tid, h = c / D;
        float a = 0.f;
#pragma unroll
        for (int i = 0; i < NW; i++) a += sacc[i][c];
        float r = a * sinv[h];
        if (CONCAT) {
            out[(size_t)node * HD + c] = r + bias[c];
        } else {
            __syncthreads();
            sacc[0][c] = r;
        }
    }
    if (!CONCAT) {
        __syncthreads();
        if (tid < D)
            out[(size_t)node * D + tid] =
                0.25f * (sacc[0][tid] + sacc[0][D + tid] + sacc[0][2 * D + tid] + sacc[0][3 * D + tid]) + bias[tid];
    }
}

// ---------------- GraphNorm reduce: float4 loads + block reduce + few atomics
// Thread owns one float4 column slice across GNB consecutive nodes. Main group
// (g0 = first node's group) accumulates in registers, block-reduced via smem,
// one atomic-set per f4 per block (same atomic count as the scalar-best).
// Rare second group (one boundary per 64-node chunk max) flushes directly.
#define GNB 64
__global__ void __launch_bounds__(256)
k_gn_reduce(const float* __restrict__ x, const int* __restrict__ batch, int F) {
    __shared__ int sb[GNB];
    __shared__ float red[256][8];
    const int tid = threadIdx.x;
    const int Fq = F >> 2;
    const int R = 256 / Fq;
    const int f4 = (tid & (Fq - 1)) * 4;
    const int r = tid / Fq;
    const int n0 = blockIdx.x * GNB;
    if (tid < GNB) sb[tid] = (n0 + tid < NN) ? batch[n0 + tid] : -1;
    __syncthreads();
    const int g0 = sb[0];
    float s0[4] = {0.f, 0.f, 0.f, 0.f}, q0[4] = {0.f, 0.f, 0.f, 0.f};
    float s1[4] = {0.f, 0.f, 0.f, 0.f}, q1[4] = {0.f, 0.f, 0.f, 0.f};
    int g1 = -1;
    for (int i = r; i < GNB && n0 + i < NN; i += R) {
        int g = sb[i];
        float4 v = *(const float4*)&x[(size_t)(n0 + i) * F + f4];
        if (g == g0) {
            s0[0] += v.x; s0[1] += v.y; s0[2] += v.z; s0[3] += v.w;
            q0[0] = fmaf(v.x, v.x, q0[0]); q0[1] = fmaf(v.y, v.y, q0[1]);
            q0[2] = fmaf(v.z, v.z, q0[2]); q0[3] = fmaf(v.w, v.w, q0[3]);
        } else {
            if (g != g1) {
                if (g1 >= 0) {
#pragma unroll
                    for (int c = 0; c < 4; c++) {
                        atomicAdd(&g_sum[g1 * F + f4 + c], s1[c]);
                        atomicAdd(&g_sq[g1 * F + f4 + c], q1[c]);
                    }
                }
#pragma unroll
                for (int c = 0; c < 4; c++) { s1[c] = 0.f; q1[c] = 0.f; }
                g1 = g;
            }
            s1[0] += v.x; s1[1] += v.y; s1[2] += v.z; s1[3] += v.w;
            q1[0] = fmaf(v.x, v.x, q1[0]); q1[1] = fmaf(v.y, v.y, q1[1]);
            q1[2] = fmaf(v.z, v.z, q1[2]); q1[3] = fmaf(v.w, v.w, q1[3]);
        }
    }
#pragma unroll
    for (int c = 0; c < 4; c++) { red[tid][c] = s0[c]; red[tid][4 + c] = q0[c]; }
    __syncthreads();
    if (r == 0) {
        float a[8];
#pragma unroll
        for (int c = 0; c < 8; c++) a[c] = red[tid][c];
        for (int j = 1; j < R; j++)
#pragma unroll
            for (int c = 0; c < 8; c++) a[c] += red[tid + j * Fq][c];
#pragma unroll
        for (int c = 0; c < 4; c++) {
            atomicAdd(&g_sum[g0 * F + f4 + c], a[c]);
            atomicAdd(&g_sq[g0 * F + f4 + c], a[4 + c]);
        }
    }
    if (g1 >= 0) {
#pragma unroll
        for (int c = 0; c < 4; c++) {
            atomicAdd(&g_sum[g1 * F + f4 + c], s1[c]);
            atomicAdd(&g_sq[g1 * F + f4 + c], q1[c]);
        }
    }
}

__global__ void k_gn_coef(const float* __restrict__ w, const float* __restrict__ b,
                          const float* __restrict__ a, int F) {
    int i = blockIdx.x * blockDim.x + threadIdx.x;
    if (i < GG * F) {
        int f = i % F;
        float c = fmaxf(g_cnt[i / F], 1.0f);
        float mean = g_sum[i] / c;
        float av = a[f];
        float var = g_sq[i] / c + mean * mean * (av * av - 2.f * av);
        var = fmaxf(var, 0.f);
        float s = w[f] * rsqrtf(var + 1e-5f);
        g_cs[i] = s;
        g_ct[i] = b[f] - s * av * mean;
        g_sum[i] = 0.f;
        g_sq[i] = 0.f;
    }
}

// apply + ReLU, emit fp16 hi/lo directly for the next GEMM's A operand
__global__ void k_gn_apply_half(const float* __restrict__ x, const int* __restrict__ batch,
                                int F) {
    int Fq = F >> 2;
    int idx = blockIdx.x * blockDim.x + threadIdx.x;
    if (idx < NN * Fq) {
        int n = idx / Fq, f4 = (idx - n * Fq) * 4;
        int g = batch[n];
        float4 xv = *(const float4*)&x[(size_t)n * F + f4];
        float4 s = *(const float4*)&g_cs[g * F + f4];
        float4 t = *(const float4*)&g_ct[g * F + f4];
        float y0 = fmaxf(fmaf(s.x, xv.x, t.x), 0.f);
        float y1 = fmaxf(fmaf(s.y, xv.y, t.y), 0.f);
        float y2 = fmaxf(fmaf(s.z, xv.z, t.z), 0.f);
        float y3 = fmaxf(fmaf(s.w, xv.w, t.w), 0.f);
        __half h0, h1, h2, h3, l0, l1, l2, l3;
        split_h(y0, h0, l0); split_h(y1, h1, l1);
        split_h(y2, h2, l2); split_h(y3, h3, l3);
        size_t o2 = ((size_t)n * F + f4) >> 1;
        ((__half2*)g_ah)[o2]     = __halves2half2(h0, h1);
        ((__half2*)g_ah)[o2 + 1] = __halves2half2(h2, h3);
        ((__half2*)g_al)[o2]     = __halves2half2(l0, l1);
        ((__half2*)g_al)[o2 + 1] = __halves2half2(l2, l3);
    }
}

// apply + ReLU + pool (layer 3, F=16)
__global__ void k_gn_apply_pool(const float* __restrict__ x, const int* __restrict__ batch) {
    const int F = 16, Fq = 4;
    int idx = blockIdx.x * blockDim.x + threadIdx.x;
    if (idx < NN * Fq) {
        int n = idx / Fq, f4 = (idx - n * Fq) * 4;
        int g = batch[n];
        float4 xv = *(const float4*)&x[(size_t)n * F + f4];
        float4 s = *(const float4*)&g_cs[g * F + f4];
        float4 t = *(const float4*)&g_ct[g * F + f4];
        atomicAdd(&g_feat[g * 16 + f4 + 0], fmaxf(fmaf(s.x, xv.x, t.x), 0.f));
        atomicAdd(&g_feat[g * 16 + f4 + 1], fmaxf(fmaf(s.y, xv.y, t.y), 0.f));
        atomicAdd(&g_feat[g * 16 + f4 + 2], fmaxf(fmaf(s.z, xv.z, t.z), 0.f));
        atomicAdd(&g_feat[g * 16 + f4 + 3], fmaxf(fmaf(s.w, xv.w, t.w), 0.f));
    }
}

// ---------------- classifier head ---------------------------------------------
__global__ void k_head(const float* __restrict__ linW, const float* __restrict__ linB,
                       float* __restrict__ out) {
    __shared__ float sf[GG * 16];
    int tid = threadIdx.x;
    if (tid < GG * 16) {
        int g = tid / 16;
        float v = g_feat[tid] / fmaxf(g_cnt[g], 1.0f);
        sf[tid] = v;
        out[GG * 4 + tid] = v;
        g_feat[tid] = 0.f;
    }
    if (tid < GG) g_cnt[tid] = 0.f;
    __syncthreads();
    if (tid < GG * 4) {
        int g = tid >> 2, c = tid & 3;
        float s = linB[c];
#pragma unroll
        for (int f = 0; f < 16; f++) s = fmaf(sf[g * 16 + f], linW[f * 4 + c], s);
        out[g * 4 + c] = s;
    }
}

// ---------------- host orchestration ------------------------------------------
static void run_gemm2(const float* bias0, const float* bias1,
                      float* C0, float* C1, int M, int K, int Nn,
                      int wbase, int wdelta) {
    __half *ah, *al;
    cudaGetSymbolAddress((void**)&ah, g_ah);
    cudaGetSymbolAddress((void**)&al, g_al);
    dim3 grid(Nn / 64, (M + 127) / 128, 2);
    k_gemm_mma<<<grid, 256>>>(ah, al, bias0, bias1, C0, C1, M, K, Nn, wbase, wdelta);
}

extern "C" void kernel_launch(void* const* d_in, const int* in_sizes, int n_in,
                              void* d_out, int out_size) {
    const float* x     = (const float*)d_in[0];
    const int*   ei    = (const int*)d_in[1];
    const int*   batch = (const int*)d_in[2];
    const float* Wl1 = (const float*)d_in[3],  *bl1 = (const float*)d_in[4];
    const float* Wr1 = (const float*)d_in[5],  *br1 = (const float*)d_in[6];
    const float* att1 = (const float*)d_in[7], *bias1 = (const float*)d_in[8];
    const float* gw1 = (const float*)d_in[9],  *gb1 = (const float*)d_in[10], *ga1 = (const float*)d_in[11];
    const float* Wl2 = (const float*)d_in[12], *bl2 = (const float*)d_in[13];
    const float* Wr2 = (const float*)d_in[14], *br2 = (const float*)d_in[15];
    const float* att2 = (const float*)d_in[16], *bias2 = (const float*)d_in[17];
    const float* gw2 = (const float*)d_in[18], *gb2 = (const float*)d_in[19], *ga2 = (const float*)d_in[20];
    const float* Wl3 = (const float*)d_in[21], *bl3 = (const float*)d_in[22];
    const float* Wr3 = (const float*)d_in[23], *br3 = (const float*)d_in[24];
    const float* att3 = (const float*)d_in[25], *bias3 = (const float*)d_in[26];
    const float* gw3 = (const float*)d_in[27], *gb3 = (const float*)d_in[28], *ga3 = (const float*)d_in[29];
    const float* linW = (const float*)d_in[30], *linB = (const float*)d_in[31];

    float *xl, *xr, *b1, *b2;
    cudaGetSymbolAddress((void**)&xl, g_xl);
    cudaGetSymbolAddress((void**)&xr, g_xr);
    cudaGetSymbolAddress((void**)&b1, g_b1);
    cudaGetSymbolAddress((void**)&b2, g_b2);

    // launches 0-2
    k_cvt<<<(NN * 32 + 255) / 256, 256>>>(x, NN * 32);
    k_cvtB_all<<<(147456 + 255) / 256, 256>>>(Wl1, Wr1, Wl2, Wr2, Wl3, Wr3);
    k_init_deg<<<(NN + 255) / 256, 256>>>();

    // launch 3: layer-1 dual GEMM (profiled position)
    run_gemm2(bl1, br1, xl, xr, NN, 128, 256, 0, WOFF);

    // CSR build
    k_count<<<(EE + 255) / 256, 256>>>(ei);
    k_scan_blk<<<NSCAN, SCAN_B>>>();
    k_scan_top<<<1, 128>>>();
    k_scan_add<<<(NN + 255) / 256, 256>>>();
    k_scatter<<<(ET + 255) / 256, 256>>>(ei);
    k_count_batch<<<(NN + 255) / 256, 256>>>(batch);

    // ---- layer 1: 128 -> 4x64 concat (256) ----
    k_attn<64, true><<<NN, 256>>>(xl, xr, att1, bias1, b1);
    k_gn_reduce<<<(NN + GNB - 1) / GNB, 256>>>(b1, batch, 256);
    k_gn_coef<<<(GG * 256 + 255) / 256, 256>>>(gw1, gb1, ga1, 256);
    k_gn_apply_half<<<(NN * 64 + 255) / 256, 256>>>(b1, batch, 256);

    // ---- layer 2: 256 -> 4x32 concat (128) ----
    run_gemm2(bl2, br2, xl, xr, NN, 256, 128, 2 * WOFF, WOFF);
    k_attn<32, true><<<NN, 128>>>(xl, xr, att2, bias2, b2);
    k_gn_reduce<<<(NN + GNB - 1) / GNB, 256>>>(b2, batch, 128);
    k_gn_coef<<<(GG * 128 + 255) / 256, 256>>>(gw2, gb2, ga2, 128);
    k_gn_apply_half<<<(NN * 32 + 255) / 256, 256>>>(b2, batch, 128);

    // ---- layer 3: 128 -> 4x16 averaged (16) ----
    run_gemm2(bl3, br3, xl, xr, NN, 128, 64, 4 * WOFF, 8192);
    k_attn<16, false><<<NN, 64>>>(xl, xr, att3, bias3, b1);
    k_gn_reduce<<<(NN + GNB - 1) / GNB, 256>>>(b1, batch, 16);
    k_gn_coef<<<(GG * 16 + 255) / 256, 256>>>(gw3, gb3, ga3, 16);
    k_gn_apply_pool<<<(NN * 4 + 255) / 256, 256>>>(b1, batch);

    // ---- head ----
    k_head<<<1, 512>>>(linW, linB, (float*)d_out);
}

// round 16
// speedup vs baseline: 1.1748x; 1.0139x over previous
#include <cuda_runtime.h>
#include <cuda_fp16.h>
#include <math.h>
#include <stdint.h>

#define NN 50000
#define EE 800000
#define ET (EE + NN)
#define GG 32
#define SCAN_B 512
#define NSCAN ((NN + SCAN_B - 1) / SCAN_B)   // 98
#define WOFF 32768

// ---------------- scratch (device globals; no allocation allowed) ----------
__device__ float  g_xl[NN * 256];
__device__ float  g_xr[NN * 256];
__device__ float  g_b1[NN * 256];
__device__ float  g_b2[NN * 256];
__device__ __half g_ah[NN * 256];     // GEMM A operand, fp16 hi
__device__ __half g_al[NN * 256];     // GEMM A operand, fp16 lo
__device__ __half g_wth[5 * WOFF];    // all transposed weights, fp16 hi
__device__ __half g_wtl[5 * WOFF];    // all transposed weights, fp16 lo
__device__ int    g_deg[NN];
__device__ int    g_rowptr[NN + 1];
__device__ int    g_cursor[NN];
__device__ int    g_csrc[ET];
__device__ int    g_bsum[128];
__device__ int    g_boff[128];
__device__ float  g_sum[GG * 256];
__device__ float  g_sq[GG * 256];
__device__ float  g_cs[GG * 256];
__device__ float  g_ct[GG * 256];
__device__ float  g_cnt[GG];
__device__ float  g_feat[GG * 16];

// ---------------- helpers ----------------------------------------------------
__device__ __forceinline__ void split_h(float v, __half& h, __half& l) {
    h = __float2half_rn(v);
    l = __float2half_rn(v - __half2float(h));
}
__device__ __forceinline__ float lrelu(float m) {
    return m > 0.f ? m : 0.2f * m;
}
__device__ __forceinline__ uint32_t smem_u32(const void* p) {
    uint32_t a;
    asm("{ .reg .u64 t; cvta.to.shared.u64 t, %1; cvt.u32.u64 %0, t; }"
        : "=r"(a) : "l"(p));
    return a;
}
__device__ __forceinline__ void cp16(uint32_t dst, const void* src, int sz) {
    asm volatile("cp.async.ca.shared.global [%0], [%1], 16, %2;"
                 :: "r"(dst), "l"(src), "r"(sz));
}
__device__ __forceinline__ void cp_commit() {
    asm volatile("cp.async.commit_group;" ::: "memory");
}
__device__ __forceinline__ void mma16816(float* c, const uint32_t* a, const uint32_t* b) {
    asm volatile(
        "mma.sync.aligned.m16n8k16.row.col.f32.f16.f16.f32 "
        "{%0,%1,%2,%3}, {%4,%5,%6,%7}, {%8,%9}, {%0,%1,%2,%3};"
        : "+f"(c[0]), "+f"(c[1]), "+f"(c[2]), "+f"(c[3])
        : "r"(a[0]), "r"(a[1]), "r"(a[2]), "r"(a[3]), "r"(b[0]), "r"(b[1]));
}

// convert fp32 buffer -> g_ah/g_al
__global__ void k_cvt(const float* __restrict__ src, int nf4) {
    int i = blockIdx.x * blockDim.x + threadIdx.x;
    if (i < nf4) {
        float4 v = ((const float4*)src)[i];
        __half h0, h1, h2, h3, l0, l1, l2, l3;
        split_h(v.x, h0, l0); split_h(v.y, h1, l1);
        split_h(v.z, h2, l2); split_h(v.w, h3, l3);
        ((__half2*)g_ah)[i * 2]     = __halves2half2(h0, h1);
        ((__half2*)g_ah)[i * 2 + 1] = __halves2half2(h2, h3);
        ((__half2*)g_al)[i * 2]     = __halves2half2(l0, l1);
        ((__half2*)g_al)[i * 2 + 1] = __halves2half2(l2, l3);
    }
}

// transpose + hi/lo split ALL six weight matrices in one launch.
__global__ void k_cvtB_all(const float* __restrict__ Wl1, const float* __restrict__ Wr1,
                           const float* __restrict__ Wl2, const float* __restrict__ Wr2,
                           const float* __restrict__ Wl3, const float* __restrict__ Wr3) {
    int i = blockIdx.x * blockDim.x + threadIdx.x;
    const float* src;
    int j, K, Nn, base;
    if (i < 32768)        { src = Wl1; j = i;          K = 128; Nn = 256; base = 0; }
    else if (i < 65536)   { src = Wr1; j = i - 32768;  K = 128; Nn = 256; base = WOFF; }
    else if (i < 98304)   { src = Wl2; j = i - 65536;  K = 256; Nn = 128; base = 2 * WOFF; }
    else if (i < 131072)  { src = Wr2; j = i - 98304;  K = 256; Nn = 128; base = 3 * WOFF; }
    else if (i < 139264)  { src = Wl3; j = i - 131072; K = 128; Nn = 64;  base = 4 * WOFF; }
    else if (i < 147456)  { src = Wr3; j = i - 139264; K = 128; Nn = 64;  base = 4 * WOFF + 8192; }
    else return;
    int k = j / Nn, n = j - k * Nn;
    float v = src[j];
    __half h, l;
    split_h(v, h, l);
    int dst = base + n * K + k;
    g_wth[dst] = h;
    g_wtl[dst] = l;
}

// ---------------- CSR build --------------------------------------------------
__global__ void k_count(const int* __restrict__ ei) {
    int e = blockIdx.x * blockDim.x + threadIdx.x;
    if (e < EE) atomicAdd(&g_deg[ei[EE + e]], 1);
}

// self-loop +1 folded in here (g_deg is zeroed: load-time zero-init, then
// re-zeroed by k_scan_add each call for replay determinism)
__global__ void k_scan_blk() {
    __shared__ int wsum[16];
    const int b = blockIdx.x, t = threadIdx.x, lane = t & 31, w = t >> 5;
    const int i = b * SCAN_B + t;
    int v = (i < NN) ? g_deg[i] + 1 : 0;
    int s = v;
#pragma unroll
    for (int o = 1; o < 32; o <<= 1) {
        int u = __shfl_up_sync(0xffffffffu, s, o);
        if (lane >= o) s += u;
    }
    if (lane == 31) wsum[w] = s;
    __syncthreads();
    if (w == 0) {
        int ws = (lane < 16) ? wsum[lane] : 0;
        int t2 = ws;
#pragma unroll
        for (int o = 1; o < 32; o <<= 1) {
            int u = __shfl_up_sync(0xffffffffu, t2, o);
            if (lane >= o) t2 += u;
        }
        if (lane < 16) wsum[lane] = t2 - ws;
    }
    __syncthreads();
    if (i < NN) g_rowptr[i] = wsum[w] + s - v;
    if (t == SCAN_B - 1) g_bsum[b] = wsum[15] + s;
}

__global__ void k_scan_top() {
    __shared__ int wsum[4];
    const int t = threadIdx.x, lane = t & 31, w = t >> 5;
    int v = (t < NSCAN) ? g_bsum[t] : 0;
    int s = v;
#pragma unroll
    for (int o = 1; o < 32; o <<= 1) {
        int u = __shfl_up_sync(0xffffffffu, s, o);
        if (lane >= o) s += u;
    }
    if (lane == 31) wsum[w] = s;
    __syncthreads();
    if (w == 0) {
        int ws = (lane < 4) ? wsum[lane] : 0;
        int t2 = ws;
#pragma unroll
        for (int o = 1; o < 32; o <<= 1) {
            int u = __shfl_up_sync(0xffffffffu, t2, o);
            if (lane >= o) t2 += u;
        }
        if (lane < 4) wsum[lane] = t2 - ws;
    }
    __syncthreads();
    if (t < NSCAN) g_boff[t] = wsum[w] + s - v;
    if (t == 127) g_rowptr[NN] = wsum[3] + s;
}

__global__ void k_scan_add() {
    int i = blockIdx.x * blockDim.x + threadIdx.x;
    if (i < NN) {
        int r = g_rowptr[i] + g_boff[i / SCAN_B];
        g_rowptr[i] = r;
        g_cursor[i] = r;
        g_deg[i] = 0;   // re-zero for next replay's k_count
    }
}

__global__ void k_scatter(const int* __restrict__ ei) {
    int e = blockIdx.x * blockDim.x + threadIdx.x;
    if (e < ET) {
        int s, d;
        if (e < EE) { s = ei[e]; d = ei[EE + e]; }
        else        { s = d = e - EE; }
        int p = atomicAdd(&g_cursor[d], 1);
        g_csrc[p] = s;
    }
}

__global__ void k_count_batch(const int* __restrict__ batch) {
    int i = blockIdx.x * blockDim.x + threadIdx.x;
    if (i < NN) atomicAdd(&g_cnt[batch[i]], 1.0f);
}

// ---------------- HMMA fp16-3x GEMM: cp.async double-buffered (R14 best) -----
#define APAD 24

__global__ void __launch_bounds__(256)
k_gemm_mma(const __half* __restrict__ Ahg, const __half* __restrict__ Alg,
           const float* __restrict__ bias0, const float* __restrict__ bias1,
           float* __restrict__ C0, float* __restrict__ C1,
           int M, int K, int Nn, int wbase, int wdelta) {
    const float* bias = blockIdx.z ? bias1 : bias0;
    float*       C    = blockIdx.z ? C1 : C0;
    const __half* WTh = g_wth + wbase + (blockIdx.z ? wdelta : 0);
    const __half* WTl = g_wtl + wbase + (blockIdx.z ? wdelta : 0);

    __shared__ alignas(16) __half Ahs[2][128 * APAD], Als[2][128 * APAD];
    __shared__ alignas(16) __half Bhs[2][64 * APAD],  Bls[2][64 * APAD];

    const int tid = threadIdx.x, lane = tid & 31, wid = tid >> 5;
    const int row0 = blockIdx.y * 128, col0 = blockIdx.x * 64;
    const int wm = wid >> 1, wn = wid & 1;
    const int fr = lane >> 2, fc = (lane & 3) * 2;

    const int ar = tid >> 1, ao = (tid & 1) * 8;
    const int bt = tid & 127, bn = bt >> 1, bko = (bt & 1) * 8;
    const __half* Wsel = (tid < 128) ? WTh : WTl;
    const int asz = (row0 + ar < M) ? 16 : 0;

    float acc[2][4][4];
#pragma unroll
    for (int i = 0; i < 2; i++)
#pragma unroll
        for (int j = 0; j < 4; j++)
#pragma unroll
            for (int q = 0; q < 4; q++) acc[i][j][q] = 0.f;

    const int nkc = K >> 4;

#define LOAD_CHUNK(kc, buf)                                                        \
    do {                                                                           \
        size_t aoff = (size_t)(row0 + ar) * K + (kc) * 16 + ao;                    \
        cp16(smem_u32(&Ahs[buf][ar * APAD + ao]), Ahg + aoff, asz);                \
        cp16(smem_u32(&Als[buf][ar * APAD + ao]), Alg + aoff, asz);                \
        __half* bd = (tid < 128) ? &Bhs[buf][bn * APAD + bko]                      \
                                 : &Bls[buf][bn * APAD + bko];                     \
        cp16(smem_u32(bd), Wsel + (size_t)(col0 + bn) * K + (kc) * 16 + bko, 16);  \
    } while (0)

    LOAD_CHUNK(0, 0);
    cp_commit();

    for (int kc = 0; kc < nkc; kc++) {
        const int cur = kc & 1;
        if (kc + 1 < nkc) {
            LOAD_CHUNK(kc + 1, cur ^ 1);
            cp_commit();
            asm volatile("cp.async.wait_group 1;" ::: "memory");
        } else {
            asm volatile("cp.async.wait_group 0;" ::: "memory");
        }
        __syncthreads();

        uint32_t ah[2][4], al[2][4], bh[4][2], bl[4][2];
#pragma unroll
        for (int ma = 0; ma < 2; ma++) {
            int r = wm * 32 + ma * 16 + fr;
            ah[ma][0] = *(const uint32_t*)&Ahs[cur][r * APAD + fc];
            ah[ma][1] = *(const uint32_t*)&Ahs[cur][(r + 8) * APAD + fc];
            ah[ma][2] = *(const uint32_t*)&Ahs[cur][r * APAD + fc + 8];
            ah[ma][3] = *(const uint32_t*)&Ahs[cur][(r + 8) * APAD + fc + 8];
            al[ma][0] = *(const uint32_t*)&Als[cur][r * APAD + fc];
            al[ma][1] = *(const uint32_t*)&Als[cur][(r + 8) * APAD + fc];
            al[ma][2] = *(const uint32_t*)&Als[cur][r * APAD + fc + 8];
            al[ma][3] = *(const uint32_t*)&Als[cur][(r + 8) * APAD + fc + 8];
        }
#pragma unroll
        for (int na = 0; na < 4; na++) {
            int cn = wn * 32 + na * 8 + fr;
            bh[na][0] = *(const uint32_t*)&Bhs[cur][cn * APAD + fc];
            bh[na][1] = *(const uint32_t*)&Bhs[cur][cn * APAD + fc + 8];
            bl[na][0] = *(const uint32_t*)&Bls[cur][cn * APAD + fc];
            bl[na][1] = *(const uint32_t*)&Bls[cur][cn * APAD + fc + 8];
        }
#pragma unroll
        for (int ma = 0; ma < 2; ma++)
#pragma unroll
            for (int na = 0; na < 4; na++) {
                mma16816(acc[ma][na], ah[ma], bh[na]);
                mma16816(acc[ma][na], ah[ma], bl[na]);
                mma16816(acc[ma][na], al[ma], bh[na]);
            }
        __syncthreads();
    }
#undef LOAD_CHUNK

#pragma unroll
    for (int ma = 0; ma < 2; ma++)
#pragma unroll
        for (int na = 0; na < 4; na++) {
            int r = row0 + wm * 32 + ma * 16 + fr;
            int c = col0 + wn * 32 + na * 8 + fc;
            float2 bb = *(const float2*)&bias[c];
            if (r < M)
                *(float2*)&C[(size_t)r * Nn + c] =
                    make_float2(acc[ma][na][0] + bb.x, acc[ma][na][1] + bb.y);
            if (r + 8 < M)
                *(float2*)&C[(size_t)(r + 8) * Nn + c] =
                    make_float2(acc[ma][na][2] + bb.x, acc[ma][na][3] + bb.y);
        }
}

// ---------------- GATv2 attention: head-aligned lanes (R12 measured-best) ----
template <int D, bool CONCAT>
__global__ void k_attn(const float* __restrict__ xl, const float* __restrict__ xr,
                       const float* __restrict__ att, const float* __restrict__ bias,
                       float* __restrict__ out) {
    constexpr int HD = 4 * D;
    constexpr int NW = HD / 32;
    const int node = blockIdx.x;
    const int tid = threadIdx.x, lane = tid & 31, w = tid >> 5;
    __shared__ float sden[NW][4];
    __shared__ float sacc[NW][HD];
    __shared__ float sinv[4];

    const int beg = g_rowptr[node], end = g_rowptr[node + 1];
    const float* xrp = xr + (size_t)node * HD;

    if (D == 64) {
        float4 rx0 = *(const float4*)&xrp[4 * lane];
        float4 rx1 = *(const float4*)&xrp[128 + 4 * lane];
        float4 ra0 = *(const float4*)&att[4 * lane];
        float4 ra1 = *(const float4*)&att[128 + 4 * lane];
        float acc0[4] = {0.f, 0.f, 0.f, 0.f}, acc1[4] = {0.f, 0.f, 0.f, 0.f};
        float dena = 0.f, denb = 0.f;
        for (int e = beg + w; e < end; e += NW) {
            const float* xs = xl + (size_t)g_csrc[e] * 256;
            float4 x0 = *(const float4*)&xs[4 * lane];
            float4 x1 = *(const float4*)&xs[128 + 4 * lane];
            float pa = lrelu(x0.x + rx0.x) * ra0.x;
            pa = fmaf(lrelu(x0.y + rx0.y), ra0.y, pa);
            pa = fmaf(lrelu(x0.z + rx0.z), ra0.z, pa);
            pa = fmaf(lrelu(x0.w + rx0.w), ra0.w, pa);
            float pb = lrelu(x1.x + rx1.x) * ra1.x;
            pb = fmaf(lrelu(x1.y + rx1.y), ra1.y, pb);
            pb = fmaf(lrelu(x1.z + rx1.z), ra1.z, pb);
            pb = fmaf(lrelu(x1.w + rx1.w), ra1.w, pb);
#pragma unroll
            for (int o = 8; o; o >>= 1) {
                pa += __shfl_xor_sync(0xffffffffu, pa, o);
                pb += __shfl_xor_sync(0xffffffffu, pb, o);
            }
            float wa = __expf(pa), wb = __expf(pb);
            dena += wa; denb += wb;
            acc0[0] = fmaf(wa, x0.x, acc0[0]); acc0[1] = fmaf(wa, x0.y, acc0[1]);
            acc0[2] = fmaf(wa, x0.z, acc0[2]); acc0[3] = fmaf(wa, x0.w, acc0[3]);
            acc1[0] = fmaf(wb, x1.x, acc1[0]); acc1[1] = fmaf(wb, x1.y, acc1[1]);
            acc1[2] = fmaf(wb, x1.z, acc1[2]); acc1[3] = fmaf(wb, x1.w, acc1[3]);
        }
        *(float4*)&sacc[w][4 * lane] = make_float4(acc0[0], acc0[1], acc0[2], acc0[3]);
        *(float4*)&sacc[w][128 + 4 * lane] = make_float4(acc1[0], acc1[1], acc1[2], acc1[3]);
        if (lane == 0)  { sden[w][0] = dena; sden[w][2] = denb; }
        if (lane == 16) { sden[w][1] = dena; sden[w][3] = denb; }
    } else if (D == 32) {
        float4 rx = *(const float4*)&xrp[4 * lane];
        float4 ra = *(const float4*)&att[4 * lane];
        float acc[4] = {0.f, 0.f, 0.f, 0.f};
        float den = 0.f;
        for (int e = beg + w; e < end; e += NW) {
            const float* xs = xl + (size_t)g_csrc[e] * 128;
            float4 x0 = *(const float4*)&xs[4 * lane];
            float p = lrelu(x0.x + rx.x) * ra.x;
            p = fmaf(lrelu(x0.y + rx.y), ra.y, p);
            p = fmaf(lrelu(x0.z + rx.z), ra.z, p);
            p = fmaf(lrelu(x0.w + rx.w), ra.w, p);
#pragma unroll
            for (int o = 4; o; o >>= 1) p += __shfl_xor_sync(0xffffffffu, p, o);
            float wg = __expf(p);
            den += wg;
            acc[0] = fmaf(wg, x0.x, acc[0]); acc[1] = fmaf(wg, x0.y, acc[1]);
            acc[2] = fmaf(wg, x0.z, acc[2]); acc[3] = fmaf(wg, x0.w, acc[3]);
        }
        *(float4*)&sacc[w][4 * lane] = make_float4(acc[0], acc[1], acc[2], acc[3]);
        if ((lane & 7) == 0) sden[w][lane >> 3] = den;
    } else {
        float2 rx = *(const float2*)&xrp[2 * lane];
        float2 ra = *(const float2*)&att[2 * lane];
        float acc[2] = {0.f, 0.f};
        float den = 0.f;
        for (int e = beg + w; e < end; e += NW) {
            const float* xs = xl + (size_t)g_csrc[e] * 64;
            float2 x0 = *(const float2*)&xs[2 * lane];
            float p = lrelu(x0.x + rx.x) * ra.x;
            p = fmaf(lrelu(x0.y + rx.y), ra.y, p);
#pragma unroll
            for (int o = 4; o; o >>= 1) p += __shfl_xor_sync(0xffffffffu, p, o);
            float wg = __expf(p);
            den += wg;
            acc[0] = fmaf(wg, x0.x, acc[0]); acc[1] = fmaf(wg, x0.y, acc[1]);
        }
        *(float2*)&sacc[w][2 * lane] = make_float2(acc[0], acc[1]);
        if ((lane & 7) == 0) sden[w][lane >> 3] = den;
    }
    __syncthreads();

    if (tid < 4) {
        float dt = 0.f;
#pragma unroll
        for (int i = 0; i < NW; i++) dt += sden[i][tid];
        sinv[tid] = 1.f / (dt + 1e-16f);
    }
    __syncthreads();

    {
        const int c = tid, h = c / D;
        float a = 0.f;
#pragma unroll
        for (int i = 0; i < NW; i++) a += sacc[i][c];
        float r = a * sinv[h];
        if (CONCAT) {
            out[(size_t)node * HD + c] = r + bias[c];
        } else {
            __syncthreads();
            sacc[0][c] = r;
        }
    }
    if (!CONCAT) {
        __syncthreads();
        if (tid < D)
            out[(size_t)node * D + tid] =
                0.25f * (sacc[0][tid] + sacc[0][D + tid] + sacc[0][2 * D + tid] + sacc[0][3 * D + tid]) + bias[tid];
    }
}

// ---------------- GraphNorm reduce (R15 measured-best) ------------------------
#define GNB 64
__global__ void __launch_bounds__(256)
k_gn_reduce(const float* __restrict__ x, const int* __restrict__ batch, int F) {
    __shared__ int sb[GNB];
    __shared__ float red[256][8];
    const int tid = threadIdx.x;
    const int Fq = F >> 2;
    const int R = 256 / Fq;
    const int f4 = (tid & (Fq - 1)) * 4;
    const int r = tid / Fq;
    const int n0 = blockIdx.x * GNB;
    if (tid < GNB) sb[tid] = (n0 + tid < NN) ? batch[n0 + tid] : -1;
    __syncthreads();
    const int g0 = sb[0];
    float s0[4] = {0.f, 0.f, 0.f, 0.f}, q0[4] = {0.f, 0.f, 0.f, 0.f};
    float s1[4] = {0.f, 0.f, 0.f, 0.f}, q1[4] = {0.f, 0.f, 0.f, 0.f};
    int g1 = -1;
    for (int i = r; i < GNB && n0 + i < NN; i += R) {
        int g = sb[i];
        float4 v = *(const float4*)&x[(size_t)(n0 + i) * F + f4];
        if (g == g0) {
            s0[0] += v.x; s0[1] += v.y; s0[2] += v.z; s0[3] += v.w;
            q0[0] = fmaf(v.x, v.x, q0[0]); q0[1] = fmaf(v.y, v.y, q0[1]);
            q0[2] = fmaf(v.z, v.z, q0[2]); q0[3] = fmaf(v.w, v.w, q0[3]);
        } else {
            if (g != g1) {
                if (g1 >= 0) {
#pragma unroll
                    for (int c = 0; c < 4; c++) {
                        atomicAdd(&g_sum[g1 * F + f4 + c], s1[c]);
                        atomicAdd(&g_sq[g1 * F + f4 + c], q1[c]);
                    }
                }
#pragma unroll
                for (int c = 0; c < 4; c++) { s1[c] = 0.f; q1[c] = 0.f; }
                g1 = g;
            }
            s1[0] += v.x; s1[1] += v.y; s1[2] += v.z; s1[3] += v.w;
            q1[0] = fmaf(v.x, v.x, q1[0]); q1[1] = fmaf(v.y, v.y, q1[1]);
            q1[2] = fmaf(v.z, v.z, q1[2]); q1[3] = fmaf(v.w, v.w, q1[3]);
        }
    }
#pragma unroll
    for (int c = 0; c < 4; c++) { red[tid][c] = s0[c]; red[tid][4 + c] = q0[c]; }
    __syncthreads();
    if (r == 0) {
        float a[8];
#pragma unroll
        for (int c = 0; c < 8; c++) a[c] = red[tid][c];
        for (int j = 1; j < R; j++)
#pragma unroll
            for (int c = 0; c < 8; c++) a[c] += red[tid + j * Fq][c];
#pragma unroll
        for (int c = 0; c < 4; c++) {
            atomicAdd(&g_sum[g0 * F + f4 + c], a[c]);
            atomicAdd(&g_sq[g0 * F + f4 + c], a[4 + c]);
        }
    }
    if (g1 >= 0) {
#pragma unroll
        for (int c = 0; c < 4; c++) {
            atomicAdd(&g_sum[g1 * F + f4 + c], s1[c]);
            atomicAdd(&g_sq[g1 * F + f4 + c], q1[c]);
        }
    }
}

__global__ void k_gn_coef(const float* __restrict__ w, const float* __restrict__ b,
                          const float* __restrict__ a, int F) {
    int i = blockIdx.x * blockDim.x + threadIdx.x;
    if (i < GG * F) {
        int f = i % F;
        float c = fmaxf(g_cnt[i / F], 1.0f);
        float mean = g_sum[i] / c;
        float av = a[f];
        float var = g_sq[i] / c + mean * mean * (av * av - 2.f * av);
        var = fmaxf(var, 0.f);
        float s = w[f] * rsqrtf(var + 1e-5f);
        g_cs[i] = s;
        g_ct[i] = b[f] - s * av * mean;
        g_sum[i] = 0.f;
        g_sq[i] = 0.f;
    }
}

// apply + ReLU, emit fp16 hi/lo directly for the next GEMM's A operand
__global__ void k_gn_apply_half(const float* __restrict__ x, const int* __restrict__ batch,
                                int F) {
    int Fq = F >> 2;
    int idx = blockIdx.x * blockDim.x + threadIdx.x;
    if (idx < NN * Fq) {
        int n = idx / Fq, f4 = (idx - n * Fq) * 4;
        int g = batch[n];
        float4 xv = *(const float4*)&x[(size_t)n * F + f4];
        float4 s = *(const float4*)&g_cs[g * F + f4];
        float4 t = *(const float4*)&g_ct[g * F + f4];
        float y0 = fmaxf(fmaf(s.x, xv.x, t.x), 0.f);
        float y1 = fmaxf(fmaf(s.y, xv.y, t.y), 0.f);
        float y2 = fmaxf(fmaf(s.z, xv.z, t.z), 0.f);
        float y3 = fmaxf(fmaf(s.w, xv.w, t.w), 0.f);
        __half h0, h1, h2, h3, l0, l1, l2, l3;
        split_h(y0, h0, l0); split_h(y1, h1, l1);
        split_h(y2, h2, l2); split_h(y3, h3, l3);
        size_t o2 = ((size_t)n * F + f4) >> 1;
        ((__half2*)g_ah)[o2]     = __halves2half2(h0, h1);
        ((__half2*)g_ah)[o2 + 1] = __halves2half2(h2, h3);
        ((__half2*)g_al)[o2]     = __halves2half2(l0, l1);
        ((__half2*)g_al)[o2 + 1] = __halves2half2(l2, l3);
    }
}

// apply + ReLU + pool (layer 3, F=16)
__global__ void k_gn_apply_pool(const float* __restrict__ x, const int* __restrict__ batch) {
    const int F = 16, Fq = 4;
    int idx = blockIdx.x * blockDim.x + threadIdx.x;
    if (idx < NN * Fq) {
        int n = idx / Fq, f4 = (idx - n * Fq) * 4;
        int g = batch[n];
        float4 xv = *(const float4*)&x[(size_t)n * F + f4];
        float4 s = *(const float4*)&g_cs[g * F + f4];
        float4 t = *(const float4*)&g_ct[g * F + f4];
        atomicAdd(&g_feat[g * 16 + f4 + 0], fmaxf(fmaf(s.x, xv.x, t.x), 0.f));
        atomicAdd(&g_feat[g * 16 + f4 + 1], fmaxf(fmaf(s.y, xv.y, t.y), 0.f));
        atomicAdd(&g_feat[g * 16 + f4 + 2], fmaxf(fmaf(s.z, xv.z, t.z), 0.f));
        atomicAdd(&g_feat[g * 16 + f4 + 3], fmaxf(fmaf(s.w, xv.w, t.w), 0.f));
    }
}

// ---------------- classifier head ---------------------------------------------
__global__ void k_head(const float* __restrict__ linW, const float* __restrict__ linB,
                       float* __restrict__ out) {
    __shared__ float sf[GG * 16];
    int tid = threadIdx.x;
    if (tid < GG * 16) {
        int g = tid / 16;
        float v = g_feat[tid] / fmaxf(g_cnt[g], 1.0f);
        sf[tid] = v;
        out[GG * 4 + tid] = v;
        g_feat[tid] = 0.f;
    }
    if (tid < GG) g_cnt[tid] = 0.f;
    __syncthreads();
    if (tid < GG * 4) {
        int g = tid >> 2, c = tid & 3;
        float s = linB[c];
#pragma unroll
        for (int f = 0; f < 16; f++) s = fmaf(sf[g * 16 + f], linW[f * 4 + c], s);
        out[g * 4 + c] = s;
    }
}

// ---------------- host orchestration ------------------------------------------
static void run_gemm2(const float* bias0, const float* bias1,
                      float* C0, float* C1, int M, int K, int Nn,
                      int wbase, int wdelta) {
    __half *ah, *al;
    cudaGetSymbolAddress((void**)&ah, g_ah);
    cudaGetSymbolAddress((void**)&al, g_al);
    dim3 grid(Nn / 64, (M + 127) / 128, 2);
    k_gemm_mma<<<grid, 256>>>(ah, al, bias0, bias1, C0, C1, M, K, Nn, wbase, wdelta);
}

extern "C" void kernel_launch(void* const* d_in, const int* in_sizes, int n_in,
                              void* d_out, int out_size) {
    const float* x     = (const float*)d_in[0];
    const int*   ei    = (const int*)d_in[1];
    const int*   batch = (const int*)d_in[2];
    const float* Wl1 = (const float*)d_in[3],  *bl1 = (const float*)d_in[4];
    const float* Wr1 = (const float*)d_in[5],  *br1 = (const float*)d_in[6];
    const float* att1 = (const float*)d_in[7], *bias1 = (const float*)d_in[8];
    const float* gw1 = (const float*)d_in[9],  *gb1 = (const float*)d_in[10], *ga1 = (const float*)d_in[11];
    const float* Wl2 = (const float*)d_in[12], *bl2 = (const float*)d_in[13];
    const float* Wr2 = (const float*)d_in[14], *br2 = (const float*)d_in[15];
    const float* att2 = (const float*)d_in[16], *bias2 = (const float*)d_in[17];
    const float* gw2 = (const float*)d_in[18], *gb2 = (const float*)d_in[19], *ga2 = (const float*)d_in[20];
    const float* Wl3 = (const float*)d_in[21], *bl3 = (const float*)d_in[22];
    const float* Wr3 = (const float*)d_in[23], *br3 = (const float*)d_in[24];
    const float* att3 = (const float*)d_in[25], *bias3 = (const float*)d_in[26];
    const float* gw3 = (const float*)d_in[27], *gb3 = (const float*)d_in[28], *ga3 = (const float*)d_in[29];
    const float* linW = (const float*)d_in[30], *linB = (const float*)d_in[31];

    float *xl, *xr, *b1, *b2;
    cudaGetSymbolAddress((void**)&xl, g_xl);
    cudaGetSymbolAddress((void**)&xr, g_xr);
    cudaGetSymbolAddress((void**)&b1, g_b1);
    cudaGetSymbolAddress((void**)&b2, g_b2);

    // ---- fork: CSR build runs concurrently with cvt + layer-1 GEMM ----
    cudaStream_t s2;
    cudaStreamCreate(&s2);
    cudaEvent_t evFork, evJoin;
    cudaEventCreateWithFlags(&evFork, cudaEventDisableTiming);
    cudaEventCreateWithFlags(&evJoin, cudaEventDisableTiming);

    cudaEventRecord(evFork, 0);
    cudaStreamWaitEvent(s2, evFork, 0);

    // side stream: CSR + batch count (independent of GEMM inputs)
    k_count<<<(EE + 255) / 256, 256, 0, s2>>>(ei);
    k_scan_blk<<<NSCAN, SCAN_B, 0, s2>>>();
    k_scan_top<<<1, 128, 0, s2>>>();
    k_scan_add<<<(NN + 255) / 256, 256, 0, s2>>>();
    k_scatter<<<(ET + 255) / 256, 256, 0, s2>>>(ei);
    k_count_batch<<<(NN + 255) / 256, 256, 0, s2>>>(batch);
    cudaEventRecord(evJoin, s2);

    // main stream: conversions + layer-1 GEMM
    k_cvt<<<(NN * 32 + 255) / 256, 256>>>(x, NN * 32);
    k_cvtB_all<<<(147456 + 255) / 256, 256>>>(Wl1, Wr1, Wl2, Wr2, Wl3, Wr3);
    run_gemm2(bl1, br1, xl, xr, NN, 128, 256, 0, WOFF);

    cudaStreamWaitEvent(0, evJoin, 0);  // join before attention

    // ---- layer 1: 128 -> 4x64 concat (256) ----
    k_attn<64, true><<<NN, 256>>>(xl, xr, att1, bias1, b1);
    k_gn_reduce<<<(NN + GNB - 1) / GNB, 256>>>(b1, batch, 256);
    k_gn_coef<<<(GG * 256 + 255) / 256, 256>>>(gw1, gb1, ga1, 256);
    k_gn_apply_half<<<(NN * 64 + 255) / 256, 256>>>(b1, batch, 256);

    // ---- layer 2: 256 -> 4x32 concat (128) ----
    run_gemm2(bl2, br2, xl, xr, NN, 256, 128, 2 * WOFF, WOFF);
    k_attn<32, true><<<NN, 128>>>(xl, xr, att2, bias2, b2);
    k_gn_reduce<<<(NN + GNB - 1) / GNB, 256>>>(b2, batch, 128);
    k_gn_coef<<<(GG * 128 + 255) / 256, 256>>>(gw2, gb2, ga2, 128);
    k_gn_apply_half<<<(NN * 32 + 255) / 256, 256>>>(b2, batch, 128);

    // ---- layer 3: 128 -> 4x16 averaged (16) ----
    run_gemm2(bl3, br3, xl, xr, NN, 128, 64, 4 * WOFF, 8192);
    k_attn<16, false><<<NN, 64>>>(xl, xr, att3, bias3, b1);
    k_gn_reduce<<<(NN + GNB - 1) / GNB, 256>>>(b1, batch, 16);
    k_gn_coef<<<(GG * 16 + 255) / 256, 256>>>(gw3, gb3, ga3, 16);
    k_gn_apply_pool<<<(NN * 4 + 255) / 256, 256>>>(b1, batch);

    // ---- head ----
    k_head<<<1, 512>>>(linW, linB, (float*)d_out);

    cudaEventDestroy(evFork);
    cudaEventDestroy(evJoin);
    cudaStreamDestroy(s2);
}

// round 17
// speedup vs baseline: 1.1960x; 1.0181x over previous
#include <cuda_runtime.h>
#include <cuda_fp16.h>
#include <math.h>
#include <stdint.h>

#define NN 50000
#define EE 800000
#define ET (EE + NN)
#define GG 32
#define SCAN_B 512
#define NSCAN ((NN + SCAN_B - 1) / SCAN_B)   // 98
#define WOFF 32768

// ---------------- scratch (device globals; no allocation allowed) ----------
__device__ float  g_xl[NN * 256];
__device__ float  g_xr[NN * 256];
__device__ float  g_b1[NN * 256];
__device__ float  g_b2[NN * 256];
__device__ __half g_wth[5 * WOFF];    // all transposed weights, fp16 hi
__device__ __half g_wtl[5 * WOFF];    // all transposed weights, fp16 lo
__device__ int    g_deg[NN];
__device__ int    g_rowptr[NN + 1];
__device__ int    g_cursor[NN];
__device__ int    g_csrc[ET];
__device__ int    g_bsum[128];
__device__ int    g_boff[128];
__device__ float  g_sum[GG * 256];
__device__ float  g_sq[GG * 256];
__device__ float  g_cs[GG * 256];
__device__ float  g_ct[GG * 256];
__device__ float  g_cnt[GG];
__device__ float  g_feat[GG * 16];

// ---------------- helpers ----------------------------------------------------
__device__ __forceinline__ void split_h(float v, __half& h, __half& l) {
    h = __float2half_rn(v);
    l = __float2half_rn(v - __half2float(h));
}
__device__ __forceinline__ float lrelu(float m) {
    return m > 0.f ? m : 0.2f * m;
}
__device__ __forceinline__ uint32_t smem_u32(const void* p) {
    uint32_t a;
    asm("{ .reg .u64 t; cvta.to.shared.u64 t, %1; cvt.u32.u64 %0, t; }"
        : "=r"(a) : "l"(p));
    return a;
}
__device__ __forceinline__ void cp16(uint32_t dst, const void* src) {
    asm volatile("cp.async.ca.shared.global [%0], [%1], 16;"
                 :: "r"(dst), "l"(src));
}
__device__ __forceinline__ void cp_commit() {
    asm volatile("cp.async.commit_group;" ::: "memory");
}
__device__ __forceinline__ void mma16816(float* c, const uint32_t* a, const uint32_t* b) {
    asm volatile(
        "mma.sync.aligned.m16n8k16.row.col.f32.f16.f16.f32 "
        "{%0,%1,%2,%3}, {%4,%5,%6,%7}, {%8,%9}, {%0,%1,%2,%3};"
        : "+f"(c[0]), "+f"(c[1]), "+f"(c[2]), "+f"(c[3])
        : "r"(a[0]), "r"(a[1]), "r"(a[2]), "r"(a[3]), "r"(b[0]), "r"(b[1]));
}

// transpose + hi/lo split ALL six weight matrices in one launch.
__global__ void k_cvtB_all(const float* __restrict__ Wl1, const float* __restrict__ Wr1,
                           const float* __restrict__ Wl2, const float* __restrict__ Wr2,
                           const float* __restrict__ Wl3, const float* __restrict__ Wr3) {
    int i = blockIdx.x * blockDim.x + threadIdx.x;
    const float* src;
    int j, K, Nn, base;
    if (i < 32768)        { src = Wl1; j = i;          K = 128; Nn = 256; base = 0; }
    else if (i < 65536)   { src = Wr1; j = i - 32768;  K = 128; Nn = 256; base = WOFF; }
    else if (i < 98304)   { src = Wl2; j = i - 65536;  K = 256; Nn = 128; base = 2 * WOFF; }
    else if (i < 131072)  { src = Wr2; j = i - 98304;  K = 256; Nn = 128; base = 3 * WOFF; }
    else if (i < 139264)  { src = Wl3; j = i - 131072; K = 128; Nn = 64;  base = 4 * WOFF; }
    else if (i < 147456)  { src = Wr3; j = i - 139264; K = 128; Nn = 64;  base = 4 * WOFF + 8192; }
    else return;
    int k = j / Nn, n = j - k * Nn;
    float v = src[j];
    __half h, l;
    split_h(v, h, l);
    int dst = base + n * K + k;
    g_wth[dst] = h;
    g_wtl[dst] = l;
}

// ---------------- CSR build --------------------------------------------------
__global__ void k_count(const int* __restrict__ ei) {
    int e = blockIdx.x * blockDim.x + threadIdx.x;
    if (e < EE) atomicAdd(&g_deg[ei[EE + e]], 1);
}

// self-loop +1 folded in; g_deg re-zeroed in k_scan_add for replay determinism
__global__ void k_scan_blk() {
    __shared__ int wsum[16];
    const int b = blockIdx.x, t = threadIdx.x, lane = t & 31, w = t >> 5;
    const int i = b * SCAN_B + t;
    int v = (i < NN) ? g_deg[i] + 1 : 0;
    int s = v;
#pragma unroll
    for (int o = 1; o < 32; o <<= 1) {
        int u = __shfl_up_sync(0xffffffffu, s, o);
        if (lane >= o) s += u;
    }
    if (lane == 31) wsum[w] = s;
    __syncthreads();
    if (w == 0) {
        int ws = (lane < 16) ? wsum[lane] : 0;
        int t2 = ws;
#pragma unroll
        for (int o = 1; o < 32; o <<= 1) {
            int u = __shfl_up_sync(0xffffffffu, t2, o);
            if (lane >= o) t2 += u;
        }
        if (lane < 16) wsum[lane] = t2 - ws;
    }
    __syncthreads();
    if (i < NN) g_rowptr[i] = wsum[w] + s - v;
    if (t == SCAN_B - 1) g_bsum[b] = wsum[15] + s;
}

__global__ void k_scan_top() {
    __shared__ int wsum[4];
    const int t = threadIdx.x, lane = t & 31, w = t >> 5;
    int v = (t < NSCAN) ? g_bsum[t] : 0;
    int s = v;
#pragma unroll
    for (int o = 1; o < 32; o <<= 1) {
        int u = __shfl_up_sync(0xffffffffu, s, o);
        if (lane >= o) s += u;
    }
    if (lane == 31) wsum[w] = s;
    __syncthreads();
    if (w == 0) {
        int ws = (lane < 4) ? wsum[lane] : 0;
        int t2 = ws;
#pragma unroll
        for (int o = 1; o < 32; o <<= 1) {
            int u = __shfl_up_sync(0xffffffffu, t2, o);
            if (lane >= o) t2 += u;
        }
        if (lane < 4) wsum[lane] = t2 - ws;
    }
    __syncthreads();
    if (t < NSCAN) g_boff[t] = wsum[w] + s - v;
    if (t == 127) g_rowptr[NN] = wsum[3] + s;
}

__global__ void k_scan_add() {
    int i = blockIdx.x * blockDim.x + threadIdx.x;
    if (i < NN) {
        int r = g_rowptr[i] + g_boff[i / SCAN_B];
        g_rowptr[i] = r;
        g_cursor[i] = r;
        g_deg[i] = 0;
    }
}

__global__ void k_scatter(const int* __restrict__ ei) {
    int e = blockIdx.x * blockDim.x + threadIdx.x;
    if (e < ET) {
        int s, d;
        if (e < EE) { s = ei[e]; d = ei[EE + e]; }
        else        { s = d = e - EE; }
        int p = atomicAdd(&g_cursor[d], 1);
        g_csrc[p] = s;
    }
}

__global__ void k_count_batch(const int* __restrict__ batch) {
    int i = blockIdx.x * blockDim.x + threadIdx.x;
    if (i < NN) atomicAdd(&g_cnt[batch[i]], 1.0f);
}

// ---------------- HMMA fp16-3x GEMM with fused GraphNorm-apply ----------------
// A is fp32; AFFINE applies y = max(cs*x+ct, 0) (layer-i coefs) during load,
// then splits hi/lo into smem. B pre-split/transposed, cp.async double-buffered.
// Tile 128x64, K-chunk 16, 256 thr (8 warps = 4Mx2N). blockIdx.z: dual (bias,C).
#define APAD 24

template <bool AFFINE>
__global__ void __launch_bounds__(256)
k_gemm_mma(const float* __restrict__ A, const int* __restrict__ batch,
           const float* __restrict__ bias0, const float* __restrict__ bias1,
           float* __restrict__ C0, float* __restrict__ C1,
           int M, int K, int Nn, int wbase, int wdelta) {
    const float* bias = blockIdx.z ? bias1 : bias0;
    float*       C    = blockIdx.z ? C1 : C0;
    const __half* WTh = g_wth + wbase + (blockIdx.z ? wdelta : 0);
    const __half* WTl = g_wtl + wbase + (blockIdx.z ? wdelta : 0);

    __shared__ alignas(16) __half Ahs[2][128 * APAD], Als[2][128 * APAD];
    __shared__ alignas(16) __half Bhs[2][64 * APAD],  Bls[2][64 * APAD];

    const int tid = threadIdx.x, lane = tid & 31, wid = tid >> 5;
    const int row0 = blockIdx.y * 128, col0 = blockIdx.x * 64;
    const int wm = wid >> 1, wn = wid & 1;
    const int fr = lane >> 2, fc = (lane & 3) * 2;

    const int ar = tid >> 1, akq = (tid & 1) * 8;    // A: row ar, 8 floats at akq
    const int bt = tid & 127, bn = bt >> 1, bko = (bt & 1) * 8;
    const __half* Wsel = (tid < 128) ? WTh : WTl;

    const int row = row0 + ar;
    const bool rok = row < M;
    int gK = 0;
    if (AFFINE) gK = batch[rok ? row : M - 1] * K;

    float acc[2][4][4];
#pragma unroll
    for (int i = 0; i < 2; i++)
#pragma unroll
        for (int j = 0; j < 4; j++)
#pragma unroll
            for (int q = 0; q < 4; q++) acc[i][j][q] = 0.f;

    const int nkc = K >> 4;

#define LOAD_B(kc, buf)                                                            \
    do {                                                                           \
        __half* bd = (tid < 128) ? &Bhs[buf][bn * APAD + bko]                      \
                                 : &Bls[buf][bn * APAD + bko];                     \
        cp16(smem_u32(bd), Wsel + (size_t)(col0 + bn) * K + (kc) * 16 + bko);      \
    } while (0)

    LOAD_B(0, 0);
    cp_commit();

    for (int kc = 0; kc < nkc; kc++) {
        const int cur = kc & 1;
        // ---- A: ldg fp32 (+fused affine/relu) + split + sts ----
        float av[8];
        if (rok) {
            const float* Ap = A + (size_t)row * K + kc * 16 + akq;
            float4 v0 = *(const float4*)Ap;
            float4 v1 = *(const float4*)(Ap + 4);
            av[0] = v0.x; av[1] = v0.y; av[2] = v0.z; av[3] = v0.w;
            av[4] = v1.x; av[5] = v1.y; av[6] = v1.z; av[7] = v1.w;
            if (AFFINE) {
                const float* csp = g_cs + gK + kc * 16 + akq;
                const float* ctp = g_ct + gK + kc * 16 + akq;
                float4 s0 = *(const float4*)csp, s1 = *(const float4*)(csp + 4);
                float4 t0 = *(const float4*)ctp, t1 = *(const float4*)(ctp + 4);
                av[0] = fmaxf(fmaf(s0.x, av[0], t0.x), 0.f);
                av[1] = fmaxf(fmaf(s0.y, av[1], t0.y), 0.f);
                av[2] = fmaxf(fmaf(s0.z, av[2], t0.z), 0.f);
                av[3] = fmaxf(fmaf(s0.w, av[3], t0.w), 0.f);
                av[4] = fmaxf(fmaf(s1.x, av[4], t1.x), 0.f);
                av[5] = fmaxf(fmaf(s1.y, av[5], t1.y), 0.f);
                av[6] = fmaxf(fmaf(s1.z, av[6], t1.z), 0.f);
                av[7] = fmaxf(fmaf(s1.w, av[7], t1.w), 0.f);
            }
        } else {
#pragma unroll
            for (int j = 0; j < 8; j++) av[j] = 0.f;
        }
        {
            int base = ar * APAD + akq;
#pragma unroll
            for (int j = 0; j < 8; j += 2) {
                __half h0, h1, l0, l1;
                split_h(av[j], h0, l0);
                split_h(av[j + 1], h1, l1);
                *(__half2*)&Ahs[cur][base + j] = __halves2half2(h0, h1);
                *(__half2*)&Als[cur][base + j] = __halves2half2(l0, l1);
            }
        }
        // ---- B: prefetch next chunk ----
        if (kc + 1 < nkc) {
            LOAD_B(kc + 1, cur ^ 1);
            cp_commit();
            asm volatile("cp.async.wait_group 1;" ::: "memory");
        } else {
            asm volatile("cp.async.wait_group 0;" ::: "memory");
        }
        __syncthreads();

        uint32_t ah[2][4], al[2][4], bh[4][2], bl[4][2];
#pragma unroll
        for (int ma = 0; ma < 2; ma++) {
            int r = wm * 32 + ma * 16 + fr;
            ah[ma][0] = *(const uint32_t*)&Ahs[cur][r * APAD + fc];
            ah[ma][1] = *(const uint32_t*)&Ahs[cur][(r + 8) * APAD + fc];
            ah[ma][2] = *(const uint32_t*)&Ahs[cur][r * APAD + fc + 8];
            ah[ma][3] = *(const uint32_t*)&Ahs[cur][(r + 8) * APAD + fc + 8];
            al[ma][0] = *(const uint32_t*)&Als[cur][r * APAD + fc];
            al[ma][1] = *(const uint32_t*)&Als[cur][(r + 8) * APAD + fc];
            al[ma][2] = *(const uint32_t*)&Als[cur][r * APAD + fc + 8];
            al[ma][3] = *(const uint32_t*)&Als[cur][(r + 8) * APAD + fc + 8];
        }
#pragma unroll
        for (int na = 0; na < 4; na++) {
            int cn = wn * 32 + na * 8 + fr;
            bh[na][0] = *(const uint32_t*)&Bhs[cur][cn * APAD + fc];
            bh[na][1] = *(const uint32_t*)&Bhs[cur][cn * APAD + fc + 8];
            bl[na][0] = *(const uint32_t*)&Bls[cur][cn * APAD + fc];
            bl[na][1] = *(const uint32_t*)&Bls[cur][cn * APAD + fc + 8];
        }
#pragma unroll
        for (int ma = 0; ma < 2; ma++)
#pragma unroll
            for (int na = 0; na < 4; na++) {
                mma16816(acc[ma][na], ah[ma], bh[na]);
                mma16816(acc[ma][na], ah[ma], bl[na]);
                mma16816(acc[ma][na], al[ma], bh[na]);
            }
        __syncthreads();
    }
#undef LOAD_B

#pragma unroll
    for (int ma = 0; ma < 2; ma++)
#pragma unroll
        for (int na = 0; na < 4; na++) {
            int r = row0 + wm * 32 + ma * 16 + fr;
            int c = col0 + wn * 32 + na * 8 + fc;
            float2 bb = *(const float2*)&bias[c];
            if (r < M)
                *(float2*)&C[(size_t)r * Nn + c] =
                    make_float2(acc[ma][na][0] + bb.x, acc[ma][na][1] + bb.y);
            if (r + 8 < M)
                *(float2*)&C[(size_t)(r + 8) * Nn + c] =
                    make_float2(acc[ma][na][2] + bb.x, acc[ma][na][3] + bb.y);
        }
}

// ---------------- GATv2 attention: head-aligned lanes (R12 measured-best) ----
template <int D, bool CONCAT>
__global__ void k_attn(const float* __restrict__ xl, const float* __restrict__ xr,
                       const float* __restrict__ att, const float* __restrict__ bias,
                       float* __restrict__ out) {
    constexpr int HD = 4 * D;
    constexpr int NW = HD / 32;
    const int node = blockIdx.x;
    const int tid = threadIdx.x, lane = tid & 31, w = tid >> 5;
    __shared__ float sden[NW][4];
    __shared__ float sacc[NW][HD];
    __shared__ float sinv[4];

    const int beg = g_rowptr[node], end = g_rowptr[node + 1];
    const float* xrp = xr + (size_t)node * HD;

    if (D == 64) {
        float4 rx0 = *(const float4*)&xrp[4 * lane];
        float4 rx1 = *(const float4*)&xrp[128 + 4 * lane];
        float4 ra0 = *(const float4*)&att[4 * lane];
        float4 ra1 = *(const float4*)&att[128 + 4 * lane];
        float acc0[4] = {0.f, 0.f, 0.f, 0.f}, acc1[4] = {0.f, 0.f, 0.f, 0.f};
        float dena = 0.f, denb = 0.f;
        for (int e = beg + w; e < end; e += NW) {
            const float* xs = xl + (size_t)g_csrc[e] * 256;
            float4 x0 = *(const float4*)&xs[4 * lane];
            float4 x1 = *(const float4*)&xs[128 + 4 * lane];
            float pa = lrelu(x0.x + rx0.x) * ra0.x;
            pa = fmaf(lrelu(x0.y + rx0.y), ra0.y, pa);
            pa = fmaf(lrelu(x0.z + rx0.z), ra0.z, pa);
            pa = fmaf(lrelu(x0.w + rx0.w), ra0.w, pa);
            float pb = lrelu(x1.x + rx1.x) * ra1.x;
            pb = fmaf(lrelu(x1.y + rx1.y), ra1.y, pb);
            pb = fmaf(lrelu(x1.z + rx1.z), ra1.z, pb);
            pb = fmaf(lrelu(x1.w + rx1.w), ra1.w, pb);
#pragma unroll
            for (int o = 8; o; o >>= 1) {
                pa += __shfl_xor_sync(0xffffffffu, pa, o);
                pb += __shfl_xor_sync(0xffffffffu, pb, o);
            }
            float wa = __expf(pa), wb = __expf(pb);
            dena += wa; denb += wb;
            acc0[0] = fmaf(wa, x0.x, acc0[0]); acc0[1] = fmaf(wa, x0.y, acc0[1]);
            acc0[2] = fmaf(wa, x0.z, acc0[2]); acc0[3] = fmaf(wa, x0.w, acc0[3]);
            acc1[0] = fmaf(wb, x1.x, acc1[0]); acc1[1] = fmaf(wb, x1.y, acc1[1]);
            acc1[2] = fmaf(wb, x1.z, acc1[2]); acc1[3] = fmaf(wb, x1.w, acc1[3]);
        }
        *(float4*)&sacc[w][4 * lane] = make_float4(acc0[0], acc0[1], acc0[2], acc0[3]);
        *(float4*)&sacc[w][128 + 4 * lane] = make_float4(acc1[0], acc1[1], acc1[2], acc1[3]);
        if (lane == 0)  { sden[w][0] = dena; sden[w][2] = denb; }
        if (lane == 16) { sden[w][1] = dena; sden[w][3] = denb; }
    } else if (D == 32) {
        float4 rx = *(const float4*)&xrp[4 * lane];
        float4 ra = *(const float4*)&att[4 * lane];
        float acc[4] = {0.f, 0.f, 0.f, 0.f};
        float den = 0.f;
        for (int e = beg + w; e < end; e += NW) {
            const float* xs = xl + (size_t)g_csrc[e] * 128;
            float4 x0 = *(const float4*)&xs[4 * lane];
            float p = lrelu(x0.x + rx.x) * ra.x;
            p = fmaf(lrelu(x0.y + rx.y), ra.y, p);
            p = fmaf(lrelu(x0.z + rx.z), ra.z, p);
            p = fmaf(lrelu(x0.w + rx.w), ra.w, p);
#pragma unroll
            for (int o = 4; o; o >>= 1) p += __shfl_xor_sync(0xffffffffu, p, o);
            float wg = __expf(p);
            den += wg;
            acc[0] = fmaf(wg, x0.x, acc[0]); acc[1] = fmaf(wg, x0.y, acc[1]);
            acc[2] = fmaf(wg, x0.z, acc[2]); acc[3] = fmaf(wg, x0.w, acc[3]);
        }
        *(float4*)&sacc[w][4 * lane] = make_float4(acc[0], acc[1], acc[2], acc[3]);
        if ((lane & 7) == 0) sden[w][lane >> 3] = den;
    } else {
        float2 rx = *(const float2*)&xrp[2 * lane];
        float2 ra = *(const float2*)&att[2 * lane];
        float acc[2] = {0.f, 0.f};
        float den = 0.f;
        for (int e = beg + w; e < end; e += NW) {
            const float* xs = xl + (size_t)g_csrc[e] * 64;
            float2 x0 = *(const float2*)&xs[2 * lane];
            float p = lrelu(x0.x + rx.x) * ra.x;
            p = fmaf(lrelu(x0.y + rx.y), ra.y, p);
#pragma unroll
            for (int o = 4; o; o >>= 1) p += __shfl_xor_sync(0xffffffffu, p, o);
            float wg = __expf(p);
            den += wg;
            acc[0] = fmaf(wg, x0.x, acc[0]); acc[1] = fmaf(wg, x0.y, acc[1]);
        }
        *(float2*)&sacc[w][2 * lane] = make_float2(acc[0], acc[1]);
        if ((lane & 7) == 0) sden[w][lane >> 3] = den;
    }
    __syncthreads();

    if (tid < 4) {
        float dt = 0.f;
#pragma unroll
        for (int i = 0; i < NW; i++) dt += sden[i][tid];
        sinv[tid] = 1.f / (dt + 1e-16f);
    }
    __syncthreads();

    {
        const int c = tid, h = c / D;
        float a = 0.f;
#pragma unroll
        for (int i = 0; i < NW; i++) a += sacc[i][c];
        float r = a * sinv[h];
        if (CONCAT) {
            out[(size_t)node * HD + c] = r + bias[c];
        } else {
            __syncthreads();
            sacc[0][c] = r;
        }
    }
    if (!CONCAT) {
        __syncthreads();
        if (tid < D)
            out[(size_t)node * D + tid] =
                0.25f * (sacc[0][tid] + sacc[0][D + tid] + sacc[0][2 * D + tid] + sacc[0][3 * D + tid]) + bias[tid];
    }
}

// ---------------- GraphNorm reduce (R15 measured-best) ------------------------
#define GNB 64
__global__ void __launch_bounds__(256)
k_gn_reduce(const float* __restrict__ x, const int* __restrict__ batch, int F) {
    __shared__ int sb[GNB];
    __shared__ float red[256][8];
    const int tid = threadIdx.x;
    const int Fq = F >> 2;
    const int R = 256 / Fq;
    const int f4 = (tid & (Fq - 1)) * 4;
    const int r = tid / Fq;
    const int n0 = blockIdx.x * GNB;
    if (tid < GNB) sb[tid] = (n0 + tid < NN) ? batch[n0 + tid] : -1;
    __syncthreads();
    const int g0 = sb[0];
    float s0[4] = {0.f, 0.f, 0.f, 0.f}, q0[4] = {0.f, 0.f, 0.f, 0.f};
    float s1[4] = {0.f, 0.f, 0.f, 0.f}, q1[4] = {0.f, 0.f, 0.f, 0.f};
    int g1 = -1;
    for (int i = r; i < GNB && n0 + i < NN; i += R) {
        int g = sb[i];
        float4 v = *(const float4*)&x[(size_t)(n0 + i) * F + f4];
        if (g == g0) {
            s0[0] += v.x; s0[1] += v.y; s0[2] += v.z; s0[3] += v.w;
            q0[0] = fmaf(v.x, v.x, q0[0]); q0[1] = fmaf(v.y, v.y, q0[1]);
            q0[2] = fmaf(v.z, v.z, q0[2]); q0[3] = fmaf(v.w, v.w, q0[3]);
        } else {
            if (g != g1) {
                if (g1 >= 0) {
#pragma unroll
                    for (int c = 0; c < 4; c++) {
                        atomicAdd(&g_sum[g1 * F + f4 + c], s1[c]);
                        atomicAdd(&g_sq[g1 * F + f4 + c], q1[c]);
                    }
                }
#pragma unroll
                for (int c = 0; c < 4; c++) { s1[c] = 0.f; q1[c] = 0.f; }
                g1 = g;
            }
            s1[0] += v.x; s1[1] += v.y; s1[2] += v.z; s1[3] += v.w;
            q1[0] = fmaf(v.x, v.x, q1[0]); q1[1] = fmaf(v.y, v.y, q1[1]);
            q1[2] = fmaf(v.z, v.z, q1[2]); q1[3] = fmaf(v.w, v.w, q1[3]);
        }
    }
#pragma unroll
    for (int c = 0; c < 4; c++) { red[tid][c] = s0[c]; red[tid][4 + c] = q0[c]; }
    __syncthreads();
    if (r == 0) {
        float a[8];
#pragma unroll
        for (int c = 0; c < 8; c++) a[c] = red[tid][c];
        for (int j = 1; j < R; j++)
#pragma unroll
            for (int c = 0; c < 8; c++) a[c] += red[tid + j * Fq][c];
#pragma unroll
        for (int c = 0; c < 4; c++) {
            atomicAdd(&g_sum[g0 * F + f4 + c], a[c]);
            atomicAdd(&g_sq[g0 * F + f4 + c], a[4 + c]);
        }
    }
    if (g1 >= 0) {
#pragma unroll
        for (int c = 0; c < 4; c++) {
            atomicAdd(&g_sum[g1 * F + f4 + c], s1[c]);
            atomicAdd(&g_sq[g1 * F + f4 + c], q1[c]);
        }
    }
}

__global__ void k_gn_coef(const float* __restrict__ w, const float* __restrict__ b,
                          const float* __restrict__ a, int F) {
    int i = blockIdx.x * blockDim.x + threadIdx.x;
    if (i < GG * F) {
        int f = i % F;
        float c = fmaxf(g_cnt[i / F], 1.0f);
        float mean = g_sum[i] / c;
        float av = a[f];
        float var = g_sq[i] / c + mean * mean * (av * av - 2.f * av);
        var = fmaxf(var, 0.f);
        float s = w[f] * rsqrtf(var + 1e-5f);
        g_cs[i] = s;
        g_ct[i] = b[f] - s * av * mean;
        g_sum[i] = 0.f;
        g_sq[i] = 0.f;
    }
}

// apply + ReLU + pool (layer 3, F=16)
__global__ void k_gn_apply_pool(const float* __restrict__ x, const int* __restrict__ batch) {
    const int F = 16, Fq = 4;
    int idx = blockIdx.x * blockDim.x + threadIdx.x;
    if (idx < NN * Fq) {
        int n = idx / Fq, f4 = (idx - n * Fq) * 4;
        int g = batch[n];
        float4 xv = *(const float4*)&x[(size_t)n * F + f4];
        float4 s = *(const float4*)&g_cs[g * F + f4];
        float4 t = *(const float4*)&g_ct[g * F + f4];
        atomicAdd(&g_feat[g * 16 + f4 + 0], fmaxf(fmaf(s.x, xv.x, t.x), 0.f));
        atomicAdd(&g_feat[g * 16 + f4 + 1], fmaxf(fmaf(s.y, xv.y, t.y), 0.f));
        atomicAdd(&g_feat[g * 16 + f4 + 2], fmaxf(fmaf(s.z, xv.z, t.z), 0.f));
        atomicAdd(&g_feat[g * 16 + f4 + 3], fmaxf(fmaf(s.w, xv.w, t.w), 0.f));
    }
}

// ---------------- classifier head ---------------------------------------------
__global__ void k_head(const float* __restrict__ linW, const float* __restrict__ linB,
                       float* __restrict__ out) {
    __shared__ float sf[GG * 16];
    int tid = threadIdx.x;
    if (tid < GG * 16) {
        int g = tid / 16;
        float v = g_feat[tid] / fmaxf(g_cnt[g], 1.0f);
        sf[tid] = v;
        out[GG * 4 + tid] = v;
        g_feat[tid] = 0.f;
    }
    if (tid < GG) g_cnt[tid] = 0.f;
    __syncthreads();
    if (tid < GG * 4) {
        int g = tid >> 2, c = tid & 3;
        float s = linB[c];
#pragma unroll
        for (int f = 0; f < 16; f++) s = fmaf(sf[g * 16 + f], linW[f * 4 + c], s);
        out[g * 4 + c] = s;
    }
}

// ---------------- host orchestration ------------------------------------------
template <bool AFFINE>
static void run_gemm2(const float* A, const int* batch,
                      const float* bias0, const float* bias1,
                      float* C0, float* C1, int M, int K, int Nn,
                      int wbase, int wdelta) {
    dim3 grid(Nn / 64, (M + 127) / 128, 2);
    k_gemm_mma<AFFINE><<<grid, 256>>>(A, batch, bias0, bias1, C0, C1, M, K, Nn,
                                      wbase, wdelta);
}

extern "C" void kernel_launch(void* const* d_in, const int* in_sizes, int n_in,
                              void* d_out, int out_size) {
    const float* x     = (const float*)d_in[0];
    const int*   ei    = (const int*)d_in[1];
    const int*   batch = (const int*)d_in[2];
    const float* Wl1 = (const float*)d_in[3],  *bl1 = (const float*)d_in[4];
    const float* Wr1 = (const float*)d_in[5],  *br1 = (const float*)d_in[6];
    const float* att1 = (const float*)d_in[7], *bias1 = (const float*)d_in[8];
    const float* gw1 = (const float*)d_in[9],  *gb1 = (const float*)d_in[10], *ga1 = (const float*)d_in[11];
    const float* Wl2 = (const float*)d_in[12], *bl2 = (const float*)d_in[13];
    const float* Wr2 = (const float*)d_in[14], *br2 = (const float*)d_in[15];
    const float* att2 = (const float*)d_in[16], *bias2 = (const float*)d_in[17];
    const float* gw2 = (const float*)d_in[18], *gb2 = (const float*)d_in[19], *ga2 = (const float*)d_in[20];
    const float* Wl3 = (const float*)d_in[21], *bl3 = (const float*)d_in[22];
    const float* Wr3 = (const float*)d_in[23], *br3 = (const float*)d_in[24];
    const float* att3 = (const float*)d_in[25], *bias3 = (const float*)d_in[26];
    const float* gw3 = (const float*)d_in[27], *gb3 = (const float*)d_in[28], *ga3 = (const float*)d_in[29];
    const float* linW = (const float*)d_in[30], *linB = (const float*)d_in[31];

    float *xl, *xr, *b1, *b2;
    cudaGetSymbolAddress((void**)&xl, g_xl);
    cudaGetSymbolAddress((void**)&xr, g_xr);
    cudaGetSymbolAddress((void**)&b1, g_b1);
    cudaGetSymbolAddress((void**)&b2, g_b2);

    // ---- fork: CSR build runs concurrently with cvtB + layer-1 GEMM ----
    cudaStream_t s2;
    cudaStreamCreate(&s2);
    cudaEvent_t evFork, evJoin;
    cudaEventCreateWithFlags(&evFork, cudaEventDisableTiming);
    cudaEventCreateWithFlags(&evJoin, cudaEventDisableTiming);

    cudaEventRecord(evFork, 0);
    cudaStreamWaitEvent(s2, evFork, 0);

    k_count<<<(EE + 255) / 256, 256, 0, s2>>>(ei);
    k_scan_blk<<<NSCAN, SCAN_B, 0, s2>>>();
    k_scan_top<<<1, 128, 0, s2>>>();
    k_scan_add<<<(NN + 255) / 256, 256, 0, s2>>>();
    k_scatter<<<(ET + 255) / 256, 256, 0, s2>>>(ei);
    k_count_batch<<<(NN + 255) / 256, 256, 0, s2>>>(batch);
    cudaEventRecord(evJoin, s2);

    // main stream: weight conversion + layer-1 GEMM (A = x fp32, no affine)
    k_cvtB_all<<<(147456 + 255) / 256, 256>>>(Wl1, Wr1, Wl2, Wr2, Wl3, Wr3);
    run_gemm2<false>(x, nullptr, bl1, br1, xl, xr, NN, 128, 256, 0, WOFF);

    cudaStreamWaitEvent(0, evJoin, 0);  // join before attention

    // ---- layer 1: 128 -> 4x64 concat (256) ----
    k_attn<64, true><<<NN, 256>>>(xl, xr, att1, bias1, b1);
    k_gn_reduce<<<(NN + GNB - 1) / GNB, 256>>>(b1, batch, 256);
    k_gn_coef<<<(GG * 256 + 255) / 256, 256>>>(gw1, gb1, ga1, 256);

    // ---- layer 2: GEMM fuses layer-1 norm apply (A = b1 fp32 + affine) ----
    run_gemm2<true>(b1, batch, bl2, br2, xl, xr, NN, 256, 128, 2 * WOFF, WOFF);
    k_attn<32, true><<<NN, 128>>>(xl, xr, att2, bias2, b2);
    k_gn_reduce<<<(NN + GNB - 1) / GNB, 256>>>(b2, batch, 128);
    k_gn_coef<<<(GG * 128 + 255) / 256, 256>>>(gw2, gb2, ga2, 128);

    // ---- layer 3: GEMM fuses layer-2 norm apply ----
    run_gemm2<true>(b2, batch, bl3, br3, xl, xr, NN, 128, 64, 4 * WOFF, 8192);
    k_attn<16, false><<<NN, 64>>>(xl, xr, att3, bias3, b1);
    k_gn_reduce<<<(NN + GNB - 1) / GNB, 256>>>(b1, batch, 16);
    k_gn_coef<<<(GG * 16 + 255) / 256, 256>>>(gw3, gb3, ga3, 16);
    k_gn_apply_pool<<<(NN * 4 + 255) / 256, 256>>>(b1, batch);

    // ---- head ----
    k_head<<<1, 512>>>(linW, linB, (float*)d_out);

    cudaEventDestroy(evFork);
    cudaEventDestroy(evJoin);
    cudaStreamDestroy(s2);
}